// round 11
// baseline (speedup 1.0000x reference)
#include <cuda_runtime.h>
#include <cuda_bf16.h>
#include <cstdint>

#define DIM 1024
#define NGROUPS 32
#define GSIZE 32
#define TT 1024
#define BB 16
#define MROWS (TT * BB)          // 16384
#define BD (BB * DIM)            // 16384

// ---------------- scratch (device globals; no allocation allowed) ----------------
__device__ float g_vx[MROWS * DIM];
__device__ float g_alpha[MROWS * DIM];
__device__ float g_delta[MROWS * DIM];
__device__ float g_compete[MROWS * DIM];
__device__ float g_xc[MROWS * DIM];          // tf32-rounded x
__device__ float g_hc[MROWS * DIM];          // tf32-rounded h[1..T]
__device__ float g_wc[4 * DIM * DIM];        // tf32-rounded [W_x, W_alpha, W_delta, W_out]

// ---------------- helpers ----------------
__device__ __forceinline__ uint32_t f2tf32(float x) {
    uint32_t r;
    asm("cvt.rna.tf32.f32 %0, %1;" : "=r"(r) : "f"(x));
    return r;
}

__device__ __forceinline__ void mma_tf32(float* c, const uint32_t* a, const uint32_t* b) {
    asm volatile(
        "mma.sync.aligned.m16n8k8.row.col.f32.tf32.tf32.f32 "
        "{%0,%1,%2,%3}, {%4,%5,%6,%7}, {%8,%9}, {%0,%1,%2,%3};"
        : "+f"(c[0]), "+f"(c[1]), "+f"(c[2]), "+f"(c[3])
        : "r"(a[0]), "r"(a[1]), "r"(a[2]), "r"(a[3]), "r"(b[0]), "r"(b[1]));
}

__device__ __forceinline__ void ldsm_x4(uint32_t& r0, uint32_t& r1, uint32_t& r2, uint32_t& r3,
                                        uint32_t addr) {
    asm volatile("ldmatrix.sync.aligned.m8n8.x4.shared.b16 {%0,%1,%2,%3}, [%4];"
                 : "=r"(r0), "=r"(r1), "=r"(r2), "=r"(r3) : "r"(addr));
}

__device__ __forceinline__ uint32_t smem_u32(const void* p) {
    uint32_t a;
    asm("{ .reg .u64 t; cvta.to.shared.u64 t, %1; cvt.u32.u64 %0, t; }" : "=r"(a) : "l"(p));
    return a;
}

__device__ __forceinline__ void cp16(uint32_t saddr, const float* gptr) {
    size_t ga = __cvta_generic_to_global(gptr);
    asm volatile("cp.async.cg.shared.global [%0], [%1], 16;" :: "r"(saddr), "l"(ga));
}

// ---------------- tf32 pre-round (elementwise) ----------------
__global__ void __launch_bounds__(256)
tf32_convert_kernel(const float* __restrict__ in, float* __restrict__ out, int n4)
{
    int i = blockIdx.x * blockDim.x + threadIdx.x;
    if (i < n4) {
        float4 v = ((const float4*)in)[i];
        uint4 o;
        o.x = f2tf32(v.x); o.y = f2tf32(v.y); o.z = f2tf32(v.z); o.w = f2tf32(v.w);
        ((uint4*)out)[i] = o;
    }
}

// ---------------- GEMM: C[M,N] = A[M,K] @ W[N,K]^T ----------------
// Block 64x128, 128 threads (4 warps, warp grid 1x4, warp tile 64x32 = R10 per-warp work).
// cp.async 3-stage pipeline, pre-rounded tf32 inputs. ~110 regs + 45KB smem
// -> 4 CTAs/SM = 16 warps/SM in FOUR independent barrier domains.
// fused=1: blockIdx.x in [0,24): wsel = x>>3 selects (W slot, bias, C, mode 0/1/2)
//   mode 0: y = acc + bias;  1: y = 1+softplus(acc+bias);  2: y = sigmoid(acc+bias)
// fused=0: mode 3: y = compete * silu(acc)
#define BM 64
#define BN 128
#define BK 16
#define LDW 20                        // smem row stride in words (80B)
#define ROWSZ (LDW * 4)               // 80 bytes
#define STAGE_A (BM * ROWSZ)          // 5120
#define STAGE_BYTES (STAGE_A + BN * ROWSZ)   // 15360 (A then B)
#define NPIPE 3
#define SMEM_GEMM (NPIPE * STAGE_BYTES)      // 46080

__global__ void __launch_bounds__(128, 4)
gemm_tf32_kernel(const float* __restrict__ A,
                 const float* __restrict__ Wc,
                 const float* __restrict__ bias0, const float* __restrict__ bias1,
                 const float* __restrict__ bias2,
                 const float* __restrict__ comp,
                 float* __restrict__ C0, float* __restrict__ C1, float* __restrict__ C2,
                 int fused)
{
    extern __shared__ char smem[];
    const int K = DIM, N = DIM;

    int mode, ntile;
    const float* W;
    const float* bias;
    float* C;
    if (fused) {
        int wsel = blockIdx.x >> 3;
        ntile = blockIdx.x & 7;
        mode = wsel;
        W    = Wc + (size_t)wsel * DIM * DIM;
        bias = (wsel == 0) ? bias0 : ((wsel == 1) ? bias1 : bias2);
        C    = (wsel == 0) ? C0 : ((wsel == 1) ? C1 : C2);
    } else {
        mode = 3; ntile = blockIdx.x; W = Wc; bias = bias0; C = C0;
    }

    const int tid  = threadIdx.x;           // 0..127
    const int lane = tid & 31;
    const int warp = tid >> 5;              // 0..3  (warpN; warpM == 0)
    const int wnBase = warp * 32;

    const int m0 = blockIdx.y * BM;
    const int n0 = ntile * BN;

    // staging: A 64 rows, 2 thr/row x 32B; B 128 rows, 1 thr/row x 64B
    const int aRow = tid >> 1;
    const int aCo  = (tid & 1) * 8;         // floats
    const float* Aptr = A + (size_t)(m0 + aRow) * K + aCo;
    const float* Wptr = W + (size_t)(n0 + tid) * K;

    const uint32_t sb = smem_u32(smem);
    const uint32_t sRowA = sb + (uint32_t)aRow * ROWSZ + (uint32_t)aCo * 4;
    const uint32_t sRowB = sb + STAGE_A + (uint32_t)tid * ROWSZ;

    // ldmatrix per-thread source row/col within a 16x8 tf32 tile
    const int lRow = (lane & 7) + ((lane >> 3) & 1) * 8;  // 0..15
    const int lK   = (lane >> 4) * 4;                     // 0 or 4
    const uint32_t aBase = sb + (uint32_t)lRow * ROWSZ + (uint32_t)lK * 4;
    const uint32_t bBase = sb + STAGE_A + (uint32_t)(wnBase + lRow) * ROWSZ + (uint32_t)lK * 4;

    float acc[4][4][4];
#pragma unroll
    for (int i = 0; i < 4; i++)
#pragma unroll
        for (int j = 0; j < 4; j++)
#pragma unroll
            for (int r = 0; r < 4; r++) acc[i][j][r] = 0.f;

    const int grp = lane >> 2;   // 0..7
    const int tig = lane & 3;    // 0..3

    const int NKT = K / BK;      // 64

    // ---- prologue: issue stages 0,1 ----
#pragma unroll
    for (int s = 0; s < NPIPE - 1; s++) {
        const uint32_t so = (uint32_t)s * STAGE_BYTES;
        const int k = s * BK;
        cp16(sRowA + so,      Aptr + k);
        cp16(sRowA + so + 16, Aptr + k + 4);
#pragma unroll
        for (int p = 0; p < 4; p++)
            cp16(sRowB + so + 16 * p, Wptr + k + 4 * p);
        asm volatile("cp.async.commit_group;");
    }

    int bufC = 0;
#pragma unroll 1
    for (int kt = 0; kt < NKT; kt++) {
        asm volatile("cp.async.wait_group 1;");   // stage kt landed (kt+1 in flight)
        __syncthreads();

        // issue stage kt+2 into buffer of kt-1 (its reads finished before the barrier)
        if (kt + 2 < NKT) {
            int bufI = bufC + 2; if (bufI >= NPIPE) bufI -= NPIPE;
            const uint32_t so = (uint32_t)bufI * STAGE_BYTES;
            const int k = (kt + 2) * BK;
            cp16(sRowA + so,      Aptr + k);
            cp16(sRowA + so + 16, Aptr + k + 4);
#pragma unroll
            for (int p = 0; p < 4; p++)
                cp16(sRowB + so + 16 * p, Wptr + k + 4 * p);
        }
        asm volatile("cp.async.commit_group;");

        // ---- compute on stage bufC: 2 k8-chunks, (4A+2B) LDSM + 16 MMA each ----
        const uint32_t so = (uint32_t)bufC * STAGE_BYTES;
        const uint32_t aB = aBase + so;
        const uint32_t bB = bBase + so;
#pragma unroll
        for (int kk = 0; kk < BK; kk += 8) {
            const uint32_t kOff = (uint32_t)kk * 4;
            uint32_t af[4][4];
#pragma unroll
            for (int mt = 0; mt < 4; mt++)
                ldsm_x4(af[mt][0], af[mt][1], af[mt][2], af[mt][3],
                        aB + (uint32_t)(mt * 16) * ROWSZ + kOff);
            uint32_t bf[4][2];
#pragma unroll
            for (int pr = 0; pr < 2; pr++)
                ldsm_x4(bf[2 * pr][0], bf[2 * pr + 1][0], bf[2 * pr][1], bf[2 * pr + 1][1],
                        bB + (uint32_t)(pr * 16) * ROWSZ + kOff);
#pragma unroll
            for (int mt = 0; mt < 4; mt++)
#pragma unroll
                for (int nt = 0; nt < 4; nt++)
                    mma_tf32(acc[mt][nt], af[mt], bf[nt]);
        }

        bufC++; if (bufC >= NPIPE) bufC -= NPIPE;
    }

    // ---- epilogue (float2 stores: reg pairs are adjacent columns) ----
#pragma unroll
    for (int mt = 0; mt < 4; mt++) {
#pragma unroll
        for (int nt = 0; nt < 4; nt++) {
#pragma unroll
            for (int half = 0; half < 2; half++) {
                int row = m0 + mt * 16 + grp + half * 8;
                int col = n0 + wnBase + nt * 8 + 2 * tig;
                float v0 = acc[mt][nt][half * 2 + 0];
                float v1 = acc[mt][nt][half * 2 + 1];
                float y0, y1;
                if (mode == 0) {
                    y0 = v0 + bias[col]; y1 = v1 + bias[col + 1];
                } else if (mode == 1) {
                    float x0 = v0 + bias[col], x1 = v1 + bias[col + 1];
                    y0 = 1.0f + ((x0 > 20.f) ? x0 : log1pf(__expf(x0)));
                    y1 = 1.0f + ((x1 > 20.f) ? x1 : log1pf(__expf(x1)));
                } else if (mode == 2) {
                    float x0 = v0 + bias[col], x1 = v1 + bias[col + 1];
                    y0 = 1.0f / (1.0f + __expf(-x0));
                    y1 = 1.0f / (1.0f + __expf(-x1));
                } else {
                    float s0 = v0 / (1.0f + __expf(-v0));
                    float s1 = v1 / (1.0f + __expf(-v1));
                    const float2 cc = *(const float2*)(comp + (size_t)row * N + col);
                    y0 = cc.x * s0; y1 = cc.y * s1;
                }
                float2 o; o.x = y0; o.y = y1;
                *(float2*)(C + (size_t)row * N + col) = o;
            }
        }
    }
}

// ---------------- scan: recurrence + fused group-softmax (compete) + tf32 h ------
// 256 blocks x 64 threads. Warp lanes = 32 consecutive d = exactly one (b,group),
// so the softmax is a pure warp reduction, off the h dependency chain.
__global__ void __launch_bounds__(64)
scan_kernel(const float* __restrict__ vx, const float* __restrict__ alpha,
            const float* __restrict__ delta, const float* __restrict__ h0,
            const float* __restrict__ r_h, float* __restrict__ out_h,
            float* __restrict__ hc, float* __restrict__ cp)
{
    int gtid = blockIdx.x * 64 + threadIdx.x;   // 0..16383
    int b = gtid >> 10;
    int d = gtid & 1023;
    size_t base = (size_t)b * DIM + d;

    float rh = r_h[d];
    float h = h0[base];
    out_h[base] = h;

    float cv[16], ca[16], cd[16], nv[16], na[16], nd[16];
#pragma unroll
    for (int i = 0; i < 16; i++) {
        size_t o = (size_t)i * BD + base;
        cv[i] = __ldcs(vx + o); ca[i] = __ldcs(alpha + o); cd[i] = __ldcs(delta + o);
    }

    for (int t0 = 0; t0 < TT; t0 += 16) {
        const bool more = (t0 + 16) < TT;
        if (more) {
#pragma unroll
            for (int i = 0; i < 16; i++) {
                size_t o = (size_t)(t0 + 16 + i) * BD + base;
                nv[i] = __ldcs(vx + o); na[i] = __ldcs(alpha + o); nd[i] = __ldcs(delta + o);
            }
        }
#pragma unroll
        for (int i = 0; i < 16; i++) {
            float v = cv[i] + rh * h;
            float av = fminf(fmaxf(fabsf(v), 1e-6f), 10.0f);
            float cand = __powf(av, ca[i]);
            cand = (v >= 0.f) ? cand : -cand;
            if (v == 0.f) cand = 0.f;     // jnp.sign(0) == 0
            h = h + cd[i] * (cand - h);
            size_t o = (size_t)(t0 + i) * BD + base;
            __stcs(out_h + o + BD, h);
            __stcs(hc + o, __uint_as_float(f2tf32(h)));
            // fused compete = softmax over the warp's 32 lanes (one group)
            float m = h;
#pragma unroll
            for (int of = 16; of > 0; of >>= 1) m = fmaxf(m, __shfl_xor_sync(0xffffffffu, m, of));
            float e = __expf(h - m);
            float s = e;
#pragma unroll
            for (int of = 16; of > 0; of >>= 1) s += __shfl_xor_sync(0xffffffffu, s, of);
            __stcs(cp + o, e / s);
        }
        if (more) {
#pragma unroll
            for (int i = 0; i < 16; i++) { cv[i] = nv[i]; ca[i] = na[i]; cd[i] = nd[i]; }
        }
    }
}

// ---------------- launch ----------------
extern "C" void kernel_launch(void* const* d_in, const int* in_sizes, int n_in,
                              void* d_out, int out_size)
{
    const float* x       = (const float*)d_in[0];   // [T,B,D]
    const float* h0      = (const float*)d_in[1];   // [B,D]
    const float* W_x     = (const float*)d_in[2];   // [D,D]
    const float* r_h     = (const float*)d_in[3];   // [D]
    const float* b       = (const float*)d_in[4];   // [D]
    const float* W_alpha = (const float*)d_in[5];
    const float* b_alpha = (const float*)d_in[6];
    const float* W_delta = (const float*)d_in[7];
    const float* b_delta = (const float*)d_in[8];
    const float* W_out   = (const float*)d_in[9];

    float* out = (float*)d_out;
    float* out_h = out;                                  // [T+1,B,D]
    float* out_y = out + (size_t)(TT + 1) * BD;          // [T,B,D]

    float *vx, *al, *dl, *cp, *xc, *hc, *wc;
    cudaGetSymbolAddress((void**)&vx, g_vx);
    cudaGetSymbolAddress((void**)&al, g_alpha);
    cudaGetSymbolAddress((void**)&dl, g_delta);
    cudaGetSymbolAddress((void**)&cp, g_compete);
    cudaGetSymbolAddress((void**)&xc, g_xc);
    cudaGetSymbolAddress((void**)&hc, g_hc);
    cudaGetSymbolAddress((void**)&wc, g_wc);

    cudaFuncSetAttribute(gemm_tf32_kernel, cudaFuncAttributeMaxDynamicSharedMemorySize,
                         SMEM_GEMM);

    // 0) pre-round inputs to tf32 bit patterns
    const int WN4 = DIM * DIM / 4;                       // 262144
    tf32_convert_kernel<<<(MROWS * DIM / 4 + 255) / 256, 256>>>(x, xc, MROWS * DIM / 4);
    tf32_convert_kernel<<<(WN4 + 255) / 256, 256>>>(W_x,     wc + 0 * DIM * DIM, WN4);
    tf32_convert_kernel<<<(WN4 + 255) / 256, 256>>>(W_alpha, wc + 1 * DIM * DIM, WN4);
    tf32_convert_kernel<<<(WN4 + 255) / 256, 256>>>(W_delta, wc + 2 * DIM * DIM, WN4);
    tf32_convert_kernel<<<(WN4 + 255) / 256, 256>>>(W_out,   wc + 3 * DIM * DIM, WN4);

    // 1) fused projections (3 weights share the x panel in L2)
    dim3 pgrid(3 * (DIM / BN), MROWS / BM);   // (24, 256)
    gemm_tf32_kernel<<<pgrid, 128, SMEM_GEMM>>>(xc, wc, b, b_alpha, b_delta,
                                                nullptr, vx, al, dl, 1);
    // 2) scan -> exact h (d_out), tf32 h (scratch), fused compete (scratch)
    scan_kernel<<<256, 64>>>(vx, al, dl, h0, r_h, out_h, hc, cp);
    // 3) output GEMM with compete*silu epilogue
    dim3 ogrid(DIM / BN, MROWS / BM);          // (8, 256)
    gemm_tf32_kernel<<<ogrid, 128, SMEM_GEMM>>>(hc, wc + 3 * (size_t)DIM * DIM,
                                                nullptr, nullptr, nullptr,
                                                cp, out_y, nullptr, nullptr, 0);
}

// round 12
// speedup vs baseline: 1.6360x; 1.6360x over previous
#include <cuda_runtime.h>
#include <cuda_bf16.h>
#include <cstdint>

#define DIM 1024
#define NGROUPS 32
#define GSIZE 32
#define TT 1024
#define BB 16
#define MROWS (TT * BB)          // 16384
#define BD (BB * DIM)            // 16384

// ---------------- scratch (device globals; no allocation allowed) ----------------
__device__ float g_vx[MROWS * DIM];
__device__ float g_alpha[MROWS * DIM];
__device__ float g_delta[MROWS * DIM];
__device__ float g_compete[MROWS * DIM];
__device__ __nv_bfloat16 g_xb[MROWS * DIM];      // bf16 x
__device__ __nv_bfloat16 g_wab[DIM * DIM];       // bf16 W_alpha
__device__ __nv_bfloat16 g_wdb[DIM * DIM];       // bf16 W_delta

// ---------------- helpers ----------------
__device__ __forceinline__ uint32_t f2tf32(float x) {
    uint32_t r;
    asm("cvt.rna.tf32.f32 %0, %1;" : "=r"(r) : "f"(x));
    return r;
}

__device__ __forceinline__ uint32_t pack_bf16x2(float lo, float hi) {
    uint32_t r;
    asm("cvt.rn.bf16x2.f32 %0, %1, %2;" : "=r"(r) : "f"(hi), "f"(lo));
    return r;
}

__device__ __forceinline__ void mma_tf32(float* c, const uint32_t* a, const uint32_t* b) {
    asm volatile(
        "mma.sync.aligned.m16n8k8.row.col.f32.tf32.tf32.f32 "
        "{%0,%1,%2,%3}, {%4,%5,%6,%7}, {%8,%9}, {%0,%1,%2,%3};"
        : "+f"(c[0]), "+f"(c[1]), "+f"(c[2]), "+f"(c[3])
        : "r"(a[0]), "r"(a[1]), "r"(a[2]), "r"(a[3]), "r"(b[0]), "r"(b[1]));
}

__device__ __forceinline__ void mma_bf16(float* c, const uint32_t* a, const uint32_t* b) {
    asm volatile(
        "mma.sync.aligned.m16n8k16.row.col.f32.bf16.bf16.f32 "
        "{%0,%1,%2,%3}, {%4,%5,%6,%7}, {%8,%9}, {%0,%1,%2,%3};"
        : "+f"(c[0]), "+f"(c[1]), "+f"(c[2]), "+f"(c[3])
        : "r"(a[0]), "r"(a[1]), "r"(a[2]), "r"(a[3]), "r"(b[0]), "r"(b[1]));
}

__device__ __forceinline__ void ldsm_x4(uint32_t& r0, uint32_t& r1, uint32_t& r2, uint32_t& r3,
                                        uint32_t addr) {
    asm volatile("ldmatrix.sync.aligned.m8n8.x4.shared.b16 {%0,%1,%2,%3}, [%4];"
                 : "=r"(r0), "=r"(r1), "=r"(r2), "=r"(r3) : "r"(addr));
}

__device__ __forceinline__ uint32_t smem_u32(const void* p) {
    uint32_t a;
    asm("{ .reg .u64 t; cvta.to.shared.u64 t, %1; cvt.u32.u64 %0, t; }" : "=r"(a) : "l"(p));
    return a;
}

// ---------------- bf16 convert (8 floats per thread) ----------------
__global__ void __launch_bounds__(256)
bf16_convert_kernel(const float* __restrict__ in, __nv_bfloat16* __restrict__ out, int n8)
{
    int i = blockIdx.x * blockDim.x + threadIdx.x;
    if (i < n8) {
        float4 a = ((const float4*)in)[2 * i];
        float4 c = ((const float4*)in)[2 * i + 1];
        uint4 o;
        o.x = pack_bf16x2(a.x, a.y); o.y = pack_bf16x2(a.z, a.w);
        o.z = pack_bf16x2(c.x, c.y); o.w = pack_bf16x2(c.z, c.w);
        ((uint4*)out)[i] = o;
    }
}

#define BM 128
#define BN 128
#define LDW 20    // smem row stride in words (80B): proven conflict-free

// ---------------- tf32 GEMM (R10-proven body): C = A @ W^T, epilogue by mode ----
// mode 0: y = acc + bias;  mode 3: y = compete * silu(acc)
__global__ void __launch_bounds__(256, 2)
gemm_tf32_kernel(const float* __restrict__ A, const float* __restrict__ W,
                 const float* __restrict__ bias, const float* __restrict__ comp,
                 float* __restrict__ C, int mode)
{
    __shared__ uint32_t As[2][BM][LDW];
    __shared__ uint32_t Bs[2][BN][LDW];

    const int K = DIM, N = DIM;
    const int tid  = threadIdx.x;
    const int lane = tid & 31;
    const int warp = tid >> 5;
    const int warpM = warp >> 2;   // 0..1
    const int warpN = warp & 3;    // 0..3
    const int wmBase = warpM * 64;
    const int wnBase = warpN * 32;

    const int m0 = blockIdx.y * BM;
    const int n0 = blockIdx.x * BN;

    const int ldRow = tid >> 2;
    const int ldCol = (tid & 3) * 4;

    const float* Aptr  = A + (size_t)(m0 + ldRow) * K + ldCol;
    const float* Aptr2 = Aptr + (size_t)64 * K;
    const float* Wptr  = W + (size_t)(n0 + ldRow) * K + ldCol;
    const float* Wptr2 = Wptr + (size_t)64 * K;

    const int lRow = (lane & 7) + ((lane >> 3) & 1) * 8;  // 0..15
    const int lK   = (lane >> 4) * 4;                     // 0 or 4

    const uint32_t AsBase = smem_u32(&As[0][0][0]);
    const uint32_t BsBase = smem_u32(&Bs[0][0][0]);

    float acc[4][4][4];
#pragma unroll
    for (int i = 0; i < 4; i++)
#pragma unroll
        for (int j = 0; j < 4; j++)
#pragma unroll
            for (int r = 0; r < 4; r++) acc[i][j][r] = 0.f;

    const int grp = lane >> 2;
    const int tig = lane & 3;

    float4 ra0 = *(const float4*)(Aptr);
    float4 ra1 = *(const float4*)(Aptr2);
    float4 rb0 = *(const float4*)(Wptr);
    float4 rb1 = *(const float4*)(Wptr2);
    {
        uint4 v;
        v.x = f2tf32(ra0.x); v.y = f2tf32(ra0.y); v.z = f2tf32(ra0.z); v.w = f2tf32(ra0.w);
        *(uint4*)&As[0][ldRow][ldCol] = v;
        v.x = f2tf32(ra1.x); v.y = f2tf32(ra1.y); v.z = f2tf32(ra1.z); v.w = f2tf32(ra1.w);
        *(uint4*)&As[0][ldRow + 64][ldCol] = v;
        v.x = f2tf32(rb0.x); v.y = f2tf32(rb0.y); v.z = f2tf32(rb0.z); v.w = f2tf32(rb0.w);
        *(uint4*)&Bs[0][ldRow][ldCol] = v;
        v.x = f2tf32(rb1.x); v.y = f2tf32(rb1.y); v.z = f2tf32(rb1.z); v.w = f2tf32(rb1.w);
        *(uint4*)&Bs[0][ldRow + 64][ldCol] = v;
    }
    __syncthreads();

    int cur = 0;
    for (int k0 = 0; k0 < K; k0 += 16) {
        const bool has_next = (k0 + 16) < K;
        if (has_next) {
            int kn = k0 + 16;
            ra0 = *(const float4*)(Aptr  + kn);
            ra1 = *(const float4*)(Aptr2 + kn);
            rb0 = *(const float4*)(Wptr  + kn);
            rb1 = *(const float4*)(Wptr2 + kn);
        }

        const uint32_t aRow = (uint32_t)(cur * BM + wmBase + lRow) * (LDW * 4);
        const uint32_t bRow = (uint32_t)(cur * BN + wnBase + lRow) * (LDW * 4);
#pragma unroll
        for (int kk = 0; kk < 16; kk += 8) {
            const uint32_t kOff = (uint32_t)(kk + lK) * 4;
            uint32_t af[4][4];
#pragma unroll
            for (int mt = 0; mt < 4; mt++) {
                uint32_t addr = AsBase + aRow + (uint32_t)(mt * 16) * (LDW * 4) + kOff;
                ldsm_x4(af[mt][0], af[mt][1], af[mt][2], af[mt][3], addr);
            }
            uint32_t bf[4][2];
#pragma unroll
            for (int pr = 0; pr < 2; pr++) {
                uint32_t addr = BsBase + bRow + (uint32_t)(pr * 16) * (LDW * 4) + kOff;
                ldsm_x4(bf[2 * pr][0], bf[2 * pr + 1][0], bf[2 * pr][1], bf[2 * pr + 1][1], addr);
            }
#pragma unroll
            for (int mt = 0; mt < 4; mt++)
#pragma unroll
                for (int nt = 0; nt < 4; nt++)
                    mma_tf32(acc[mt][nt], af[mt], bf[nt]);
        }

        if (has_next) {
            int nxt = cur ^ 1;
            uint4 v;
            v.x = f2tf32(ra0.x); v.y = f2tf32(ra0.y); v.z = f2tf32(ra0.z); v.w = f2tf32(ra0.w);
            *(uint4*)&As[nxt][ldRow][ldCol] = v;
            v.x = f2tf32(ra1.x); v.y = f2tf32(ra1.y); v.z = f2tf32(ra1.z); v.w = f2tf32(ra1.w);
            *(uint4*)&As[nxt][ldRow + 64][ldCol] = v;
            v.x = f2tf32(rb0.x); v.y = f2tf32(rb0.y); v.z = f2tf32(rb0.z); v.w = f2tf32(rb0.w);
            *(uint4*)&Bs[nxt][ldRow][ldCol] = v;
            v.x = f2tf32(rb1.x); v.y = f2tf32(rb1.y); v.z = f2tf32(rb1.z); v.w = f2tf32(rb1.w);
            *(uint4*)&Bs[nxt][ldRow + 64][ldCol] = v;
        }
        __syncthreads();
        cur ^= 1;
    }

#pragma unroll
    for (int mt = 0; mt < 4; mt++) {
#pragma unroll
        for (int nt = 0; nt < 4; nt++) {
#pragma unroll
            for (int half = 0; half < 2; half++) {
                int row = m0 + wmBase + mt * 16 + grp + half * 8;
                int col = n0 + wnBase + nt * 8 + 2 * tig;
                float v0 = acc[mt][nt][half * 2 + 0];
                float v1 = acc[mt][nt][half * 2 + 1];
                float y0, y1;
                if (mode == 0) {
                    y0 = v0 + bias[col]; y1 = v1 + bias[col + 1];
                } else {
                    float s0 = v0 / (1.0f + __expf(-v0));
                    float s1 = v1 / (1.0f + __expf(-v1));
                    const float2 cc = *(const float2*)(comp + (size_t)row * N + col);
                    y0 = cc.x * s0; y1 = cc.y * s1;
                }
                float2 o; o.x = y0; o.y = y1;
                *(float2*)(C + (size_t)row * N + col) = o;
            }
        }
    }
}

// ---------------- bf16 GEMM (R3 structure, BK=32, m16n8k16) ----------------
// fused alpha+delta: blockIdx.x in [0,16): wsel = x>>3:
//   0 -> W=Wa, bias=ba, mode 1: y = 1+softplus(acc+bias)
//   1 -> W=Wd, bias=bd, mode 2: y = sigmoid(acc+bias)
#define BKB 32

__global__ void __launch_bounds__(256, 2)
gemm_bf16_kernel(const __nv_bfloat16* __restrict__ Xb,
                 const __nv_bfloat16* __restrict__ Wa, const __nv_bfloat16* __restrict__ Wd,
                 const float* __restrict__ ba, const float* __restrict__ bd,
                 float* __restrict__ Ca, float* __restrict__ Cd)
{
    __shared__ uint32_t As[2][BM][LDW];
    __shared__ uint32_t Bs[2][BN][LDW];

    const int K = DIM, N = DIM;

    const int wsel = blockIdx.x >> 3;
    const int ntile = blockIdx.x & 7;
    const __nv_bfloat16* W = wsel ? Wd : Wa;
    const float* bias = wsel ? bd : ba;
    float* C = wsel ? Cd : Ca;

    const int tid  = threadIdx.x;
    const int lane = tid & 31;
    const int warp = tid >> 5;
    const int warpM = warp >> 2;   // 0..1
    const int warpN = warp & 3;    // 0..3
    const int wmBase = warpM * 64;
    const int wnBase = warpN * 32;

    const int m0 = blockIdx.y * BM;
    const int n0 = ntile * BN;

    // staging: 4 threads/row, 16B (8 bf16) chunks; rows (tid>>2) in two passes (+0,+64)
    const int ldRow = tid >> 2;           // 0..63
    const int ldCh  = (tid & 3);          // chunk 0..3 -> bf16 elem offset 8*ldCh
    // uint4 = 8 bf16; row has 4 chunks of 8 bf16 = 32 bf16 = BKB
    const __nv_bfloat16* Aptr  = Xb + (size_t)(m0 + ldRow) * K + ldCh * 8;
    const __nv_bfloat16* Aptr2 = Aptr + (size_t)64 * K;
    const __nv_bfloat16* Wptr  = W + (size_t)(n0 + ldRow) * K + ldCh * 8;
    const __nv_bfloat16* Wptr2 = Wptr + (size_t)64 * K;

    const uint32_t AsBase = smem_u32(&As[0][0][0]);
    const uint32_t BsBase = smem_u32(&Bs[0][0][0]);

    // ldmatrix A address pattern (16x16 bf16 tile): row 0..15, k-half byte 0/16
    const int lRow = (lane & 7) + ((lane >> 3) & 1) * 8;   // 0..15
    const int lKA  = (lane >> 4) * 16;                     // bytes
    // ldmatrix B pattern (two n8 tiles per x4): row 0..15, k-half byte 0/16
    const int bRowL = (lane & 7) + ((lane >> 4) << 3);     // 0..15
    const int lKB   = ((lane >> 3) & 1) * 16;              // bytes

    float acc[4][4][4];
#pragma unroll
    for (int i = 0; i < 4; i++)
#pragma unroll
        for (int j = 0; j < 4; j++)
#pragma unroll
            for (int r = 0; r < 4; r++) acc[i][j][r] = 0.f;

    const int grp = lane >> 2;
    const int tig = lane & 3;

    // ---- prologue: stage k0=0 into buffer 0 ----
    uint4 qa0 = *(const uint4*)(Aptr);
    uint4 qa1 = *(const uint4*)(Aptr2);
    uint4 qb0 = *(const uint4*)(Wptr);
    uint4 qb1 = *(const uint4*)(Wptr2);
    {
        *(uint4*)&As[0][ldRow][ldCh * 4]      = qa0;
        *(uint4*)&As[0][ldRow + 64][ldCh * 4] = qa1;
        *(uint4*)&Bs[0][ldRow][ldCh * 4]      = qb0;
        *(uint4*)&Bs[0][ldRow + 64][ldCh * 4] = qb1;
    }
    __syncthreads();

    int cur = 0;
    for (int k0 = 0; k0 < K; k0 += BKB) {
        const bool has_next = (k0 + BKB) < K;
        if (has_next) {
            int kn = k0 + BKB;
            qa0 = *(const uint4*)(Aptr  + kn);
            qa1 = *(const uint4*)(Aptr2 + kn);
            qb0 = *(const uint4*)(Wptr  + kn);
            qb1 = *(const uint4*)(Wptr2 + kn);
        }

        // ---- compute: 2 k16 steps ----
        const uint32_t aRow = (uint32_t)(cur * BM + wmBase + lRow) * (LDW * 4);
        const uint32_t bRow = (uint32_t)(cur * BN + wnBase + bRowL) * (LDW * 4);
#pragma unroll
        for (int kk = 0; kk < 2; kk++) {
            const uint32_t kByte = (uint32_t)kk * 32;
            uint32_t af[4][4];
#pragma unroll
            for (int mt = 0; mt < 4; mt++) {
                uint32_t addr = AsBase + aRow + (uint32_t)(mt * 16) * (LDW * 4) + kByte + lKA;
                ldsm_x4(af[mt][0], af[mt][1], af[mt][2], af[mt][3], addr);
            }
            uint32_t bf[4][2];
#pragma unroll
            for (int pr = 0; pr < 2; pr++) {
                uint32_t addr = BsBase + bRow + (uint32_t)(pr * 16) * (LDW * 4) + kByte + lKB;
                ldsm_x4(bf[2 * pr][0], bf[2 * pr][1], bf[2 * pr + 1][0], bf[2 * pr + 1][1], addr);
            }
#pragma unroll
            for (int mt = 0; mt < 4; mt++)
#pragma unroll
                for (int nt = 0; nt < 4; nt++)
                    mma_bf16(acc[mt][nt], af[mt], bf[nt]);
        }

        if (has_next) {
            int nxt = cur ^ 1;
            *(uint4*)&As[nxt][ldRow][ldCh * 4]      = qa0;
            *(uint4*)&As[nxt][ldRow + 64][ldCh * 4] = qa1;
            *(uint4*)&Bs[nxt][ldRow][ldCh * 4]      = qb0;
            *(uint4*)&Bs[nxt][ldRow + 64][ldCh * 4] = qb1;
        }
        __syncthreads();
        cur ^= 1;
    }

    // ---- epilogue ----
#pragma unroll
    for (int mt = 0; mt < 4; mt++) {
#pragma unroll
        for (int nt = 0; nt < 4; nt++) {
#pragma unroll
            for (int half = 0; half < 2; half++) {
                int row = m0 + wmBase + mt * 16 + grp + half * 8;
                int col = n0 + wnBase + nt * 8 + 2 * tig;
                float x0 = acc[mt][nt][half * 2 + 0] + bias[col];
                float x1 = acc[mt][nt][half * 2 + 1] + bias[col + 1];
                float y0, y1;
                if (wsel == 0) {
                    y0 = 1.0f + ((x0 > 20.f) ? x0 : log1pf(__expf(x0)));
                    y1 = 1.0f + ((x1 > 20.f) ? x1 : log1pf(__expf(x1)));
                } else {
                    y0 = 1.0f / (1.0f + __expf(-x0));
                    y1 = 1.0f / (1.0f + __expf(-x1));
                }
                float2 o; o.x = y0; o.y = y1;
                *(float2*)(C + (size_t)row * N + col) = o;
            }
        }
    }
}

// ---------------- scan: recurrence + fused group-softmax (compete) ----------------
// 256 blocks x 64 threads; warp lanes = one (b,group) -> softmax is a warp reduction.
__global__ void __launch_bounds__(64)
scan_kernel(const float* __restrict__ vx, const float* __restrict__ alpha,
            const float* __restrict__ delta, const float* __restrict__ h0,
            const float* __restrict__ r_h, float* __restrict__ out_h,
            float* __restrict__ cp)
{
    int gtid = blockIdx.x * 64 + threadIdx.x;   // 0..16383
    int b = gtid >> 10;
    int d = gtid & 1023;
    size_t base = (size_t)b * DIM + d;

    float rh = r_h[d];
    float h = h0[base];
    out_h[base] = h;

    float cv[16], ca[16], cd[16], nv[16], na[16], nd[16];
#pragma unroll
    for (int i = 0; i < 16; i++) {
        size_t o = (size_t)i * BD + base;
        cv[i] = __ldcs(vx + o); ca[i] = __ldcs(alpha + o); cd[i] = __ldcs(delta + o);
    }

    for (int t0 = 0; t0 < TT; t0 += 16) {
        const bool more = (t0 + 16) < TT;
        if (more) {
#pragma unroll
            for (int i = 0; i < 16; i++) {
                size_t o = (size_t)(t0 + 16 + i) * BD + base;
                nv[i] = __ldcs(vx + o); na[i] = __ldcs(alpha + o); nd[i] = __ldcs(delta + o);
            }
        }
#pragma unroll
        for (int i = 0; i < 16; i++) {
            float v = cv[i] + rh * h;
            float av = fminf(fmaxf(fabsf(v), 1e-6f), 10.0f);
            float cand = __powf(av, ca[i]);
            cand = (v >= 0.f) ? cand : -cand;
            if (v == 0.f) cand = 0.f;     // jnp.sign(0) == 0
            h = h + cd[i] * (cand - h);
            size_t o = (size_t)(t0 + i) * BD + base;
            __stcs(out_h + o + BD, h);
            // fused compete = softmax over the warp's 32 lanes (one group)
            float m = h;
#pragma unroll
            for (int of = 16; of > 0; of >>= 1) m = fmaxf(m, __shfl_xor_sync(0xffffffffu, m, of));
            float e = __expf(h - m);
            float s = e;
#pragma unroll
            for (int of = 16; of > 0; of >>= 1) s += __shfl_xor_sync(0xffffffffu, s, of);
            __stcs(cp + o, e / s);
        }
        if (more) {
#pragma unroll
            for (int i = 0; i < 16; i++) { cv[i] = nv[i]; ca[i] = na[i]; cd[i] = nd[i]; }
        }
    }
}

// ---------------- launch ----------------
extern "C" void kernel_launch(void* const* d_in, const int* in_sizes, int n_in,
                              void* d_out, int out_size)
{
    const float* x       = (const float*)d_in[0];   // [T,B,D]
    const float* h0      = (const float*)d_in[1];   // [B,D]
    const float* W_x     = (const float*)d_in[2];   // [D,D]
    const float* r_h     = (const float*)d_in[3];   // [D]
    const float* b       = (const float*)d_in[4];   // [D]
    const float* W_alpha = (const float*)d_in[5];
    const float* b_alpha = (const float*)d_in[6];
    const float* W_delta = (const float*)d_in[7];
    const float* b_delta = (const float*)d_in[8];
    const float* W_out   = (const float*)d_in[9];

    float* out = (float*)d_out;
    float* out_h = out;                                  // [T+1,B,D]
    float* out_y = out + (size_t)(TT + 1) * BD;          // [T,B,D]

    float *vx, *al, *dl, *cpt;
    __nv_bfloat16 *xb, *wab, *wdb;
    cudaGetSymbolAddress((void**)&vx, g_vx);
    cudaGetSymbolAddress((void**)&al, g_alpha);
    cudaGetSymbolAddress((void**)&dl, g_delta);
    cudaGetSymbolAddress((void**)&cpt, g_compete);
    cudaGetSymbolAddress((void**)&xb, g_xb);
    cudaGetSymbolAddress((void**)&wab, g_wab);
    cudaGetSymbolAddress((void**)&wdb, g_wdb);

    // 0) bf16 converts for the alpha/delta path
    const int XN8 = MROWS * DIM / 8;                     // 2M
    const int WN8 = DIM * DIM / 8;                       // 131072
    bf16_convert_kernel<<<(XN8 + 255) / 256, 256>>>(x, xb, XN8);
    bf16_convert_kernel<<<(WN8 + 255) / 256, 256>>>(W_alpha, wab, WN8);
    bf16_convert_kernel<<<(WN8 + 255) / 256, 256>>>(W_delta, wdb, WN8);

    // 1) vx projection (tf32, proven kernel)
    dim3 vgrid(DIM / BN, MROWS / BM);          // (8, 128)
    gemm_tf32_kernel<<<vgrid, 256>>>(x, W_x, b, nullptr, vx, 0);

    // 2) alpha + delta projections (bf16, half the tensor/LDSM work)
    dim3 agrid(2 * (DIM / BN), MROWS / BM);    // (16, 128)
    gemm_bf16_kernel<<<agrid, 256>>>(xb, wab, wdb, b_alpha, b_delta, al, dl);

    // 3) sequential scan + fused compete softmax
    scan_kernel<<<256, 64>>>(vx, al, dl, h0, r_h, out_h, cpt);

    // 4) output GEMM with compete*silu epilogue (tf32)
    gemm_tf32_kernel<<<vgrid, 256>>>(out_h + BD, W_out, nullptr, cpt, out_y, 3);
}

// round 13
// speedup vs baseline: 1.6522x; 1.0099x over previous
#include <cuda_runtime.h>
#include <cuda_bf16.h>
#include <cstdint>

#define DIM 1024
#define NGROUPS 32
#define GSIZE 32
#define TT 1024
#define BB 16
#define MROWS (TT * BB)          // 16384
#define BD (BB * DIM)            // 16384

// ---------------- scratch (device globals; no allocation allowed) ----------------
__device__ float g_vx[MROWS * DIM];
__device__ float g_alpha[MROWS * DIM];
__device__ float g_delta[MROWS * DIM];
__device__ float g_compete[MROWS * DIM];
__device__ __nv_bfloat16 g_xb[MROWS * DIM];      // bf16 x
__device__ __nv_bfloat16 g_wab[DIM * DIM];       // bf16 W_alpha
__device__ __nv_bfloat16 g_wdb[DIM * DIM];       // bf16 W_delta

// ---------------- helpers ----------------
__device__ __forceinline__ uint32_t f2tf32(float x) {
    uint32_t r;
    asm("cvt.rna.tf32.f32 %0, %1;" : "=r"(r) : "f"(x));
    return r;
}

__device__ __forceinline__ uint32_t pack_bf16x2(float lo, float hi) {
    uint32_t r;
    asm("cvt.rn.bf16x2.f32 %0, %1, %2;" : "=r"(r) : "f"(hi), "f"(lo));
    return r;
}

__device__ __forceinline__ void mma_tf32(float* c, const uint32_t* a, const uint32_t* b) {
    asm volatile(
        "mma.sync.aligned.m16n8k8.row.col.f32.tf32.tf32.f32 "
        "{%0,%1,%2,%3}, {%4,%5,%6,%7}, {%8,%9}, {%0,%1,%2,%3};"
        : "+f"(c[0]), "+f"(c[1]), "+f"(c[2]), "+f"(c[3])
        : "r"(a[0]), "r"(a[1]), "r"(a[2]), "r"(a[3]), "r"(b[0]), "r"(b[1]));
}

__device__ __forceinline__ void mma_bf16(float* c, const uint32_t* a, const uint32_t* b) {
    asm volatile(
        "mma.sync.aligned.m16n8k16.row.col.f32.bf16.bf16.f32 "
        "{%0,%1,%2,%3}, {%4,%5,%6,%7}, {%8,%9}, {%0,%1,%2,%3};"
        : "+f"(c[0]), "+f"(c[1]), "+f"(c[2]), "+f"(c[3])
        : "r"(a[0]), "r"(a[1]), "r"(a[2]), "r"(a[3]), "r"(b[0]), "r"(b[1]));
}

__device__ __forceinline__ void ldsm_x4(uint32_t& r0, uint32_t& r1, uint32_t& r2, uint32_t& r3,
                                        uint32_t addr) {
    asm volatile("ldmatrix.sync.aligned.m8n8.x4.shared.b16 {%0,%1,%2,%3}, [%4];"
                 : "=r"(r0), "=r"(r1), "=r"(r2), "=r"(r3) : "r"(addr));
}

__device__ __forceinline__ uint32_t smem_u32(const void* p) {
    uint32_t a;
    asm("{ .reg .u64 t; cvta.to.shared.u64 t, %1; cvt.u32.u64 %0, t; }" : "=r"(a) : "l"(p));
    return a;
}

// ---------------- bf16 convert (8 floats per thread) ----------------
__global__ void __launch_bounds__(256)
bf16_convert_kernel(const float* __restrict__ in, __nv_bfloat16* __restrict__ out, int n8)
{
    int i = blockIdx.x * blockDim.x + threadIdx.x;
    if (i < n8) {
        float4 a = ((const float4*)in)[2 * i];
        float4 c = ((const float4*)in)[2 * i + 1];
        uint4 o;
        o.x = pack_bf16x2(a.x, a.y); o.y = pack_bf16x2(a.z, a.w);
        o.z = pack_bf16x2(c.x, c.y); o.w = pack_bf16x2(c.z, c.w);
        ((uint4*)out)[i] = o;
    }
}

#define BM 128
#define BN 128
#define LDW 20    // smem row stride in words (80B): proven conflict-free

// ---------------- tf32 GEMM (proven body): C = A @ W^T, epilogue by mode ----
// mode 0: y = acc + bias;  mode 3: y = compete * silu(acc)
__global__ void __launch_bounds__(256, 2)
gemm_tf32_kernel(const float* __restrict__ A, const float* __restrict__ W,
                 const float* __restrict__ bias, const float* __restrict__ comp,
                 float* __restrict__ C, int mode)
{
    __shared__ uint32_t As[2][BM][LDW];
    __shared__ uint32_t Bs[2][BN][LDW];

    const int K = DIM, N = DIM;
    const int tid  = threadIdx.x;
    const int lane = tid & 31;
    const int warp = tid >> 5;
    const int warpM = warp >> 2;   // 0..1
    const int warpN = warp & 3;    // 0..3
    const int wmBase = warpM * 64;
    const int wnBase = warpN * 32;

    const int m0 = blockIdx.y * BM;
    const int n0 = blockIdx.x * BN;

    const int ldRow = tid >> 2;
    const int ldCol = (tid & 3) * 4;

    const float* Aptr  = A + (size_t)(m0 + ldRow) * K + ldCol;
    const float* Aptr2 = Aptr + (size_t)64 * K;
    const float* Wptr  = W + (size_t)(n0 + ldRow) * K + ldCol;
    const float* Wptr2 = Wptr + (size_t)64 * K;

    const int lRow = (lane & 7) + ((lane >> 3) & 1) * 8;  // 0..15
    const int lK   = (lane >> 4) * 4;                     // 0 or 4

    const uint32_t AsBase = smem_u32(&As[0][0][0]);
    const uint32_t BsBase = smem_u32(&Bs[0][0][0]);

    float acc[4][4][4];
#pragma unroll
    for (int i = 0; i < 4; i++)
#pragma unroll
        for (int j = 0; j < 4; j++)
#pragma unroll
            for (int r = 0; r < 4; r++) acc[i][j][r] = 0.f;

    const int grp = lane >> 2;
    const int tig = lane & 3;

    float4 ra0 = *(const float4*)(Aptr);
    float4 ra1 = *(const float4*)(Aptr2);
    float4 rb0 = *(const float4*)(Wptr);
    float4 rb1 = *(const float4*)(Wptr2);
    {
        uint4 v;
        v.x = f2tf32(ra0.x); v.y = f2tf32(ra0.y); v.z = f2tf32(ra0.z); v.w = f2tf32(ra0.w);
        *(uint4*)&As[0][ldRow][ldCol] = v;
        v.x = f2tf32(ra1.x); v.y = f2tf32(ra1.y); v.z = f2tf32(ra1.z); v.w = f2tf32(ra1.w);
        *(uint4*)&As[0][ldRow + 64][ldCol] = v;
        v.x = f2tf32(rb0.x); v.y = f2tf32(rb0.y); v.z = f2tf32(rb0.z); v.w = f2tf32(rb0.w);
        *(uint4*)&Bs[0][ldRow][ldCol] = v;
        v.x = f2tf32(rb1.x); v.y = f2tf32(rb1.y); v.z = f2tf32(rb1.z); v.w = f2tf32(rb1.w);
        *(uint4*)&Bs[0][ldRow + 64][ldCol] = v;
    }
    __syncthreads();

    int cur = 0;
    for (int k0 = 0; k0 < K; k0 += 16) {
        const bool has_next = (k0 + 16) < K;
        if (has_next) {
            int kn = k0 + 16;
            ra0 = *(const float4*)(Aptr  + kn);
            ra1 = *(const float4*)(Aptr2 + kn);
            rb0 = *(const float4*)(Wptr  + kn);
            rb1 = *(const float4*)(Wptr2 + kn);
        }

        const uint32_t aRow = (uint32_t)(cur * BM + wmBase + lRow) * (LDW * 4);
        const uint32_t bRow = (uint32_t)(cur * BN + wnBase + lRow) * (LDW * 4);
#pragma unroll
        for (int kk = 0; kk < 16; kk += 8) {
            const uint32_t kOff = (uint32_t)(kk + lK) * 4;
            uint32_t af[4][4];
#pragma unroll
            for (int mt = 0; mt < 4; mt++) {
                uint32_t addr = AsBase + aRow + (uint32_t)(mt * 16) * (LDW * 4) + kOff;
                ldsm_x4(af[mt][0], af[mt][1], af[mt][2], af[mt][3], addr);
            }
            uint32_t bf[4][2];
#pragma unroll
            for (int pr = 0; pr < 2; pr++) {
                uint32_t addr = BsBase + bRow + (uint32_t)(pr * 16) * (LDW * 4) + kOff;
                ldsm_x4(bf[2 * pr][0], bf[2 * pr + 1][0], bf[2 * pr][1], bf[2 * pr + 1][1], addr);
            }
#pragma unroll
            for (int mt = 0; mt < 4; mt++)
#pragma unroll
                for (int nt = 0; nt < 4; nt++)
                    mma_tf32(acc[mt][nt], af[mt], bf[nt]);
        }

        if (has_next) {
            int nxt = cur ^ 1;
            uint4 v;
            v.x = f2tf32(ra0.x); v.y = f2tf32(ra0.y); v.z = f2tf32(ra0.z); v.w = f2tf32(ra0.w);
            *(uint4*)&As[nxt][ldRow][ldCol] = v;
            v.x = f2tf32(ra1.x); v.y = f2tf32(ra1.y); v.z = f2tf32(ra1.z); v.w = f2tf32(ra1.w);
            *(uint4*)&As[nxt][ldRow + 64][ldCol] = v;
            v.x = f2tf32(rb0.x); v.y = f2tf32(rb0.y); v.z = f2tf32(rb0.z); v.w = f2tf32(rb0.w);
            *(uint4*)&Bs[nxt][ldRow][ldCol] = v;
            v.x = f2tf32(rb1.x); v.y = f2tf32(rb1.y); v.z = f2tf32(rb1.z); v.w = f2tf32(rb1.w);
            *(uint4*)&Bs[nxt][ldRow + 64][ldCol] = v;
        }
        __syncthreads();
        cur ^= 1;
    }

#pragma unroll
    for (int mt = 0; mt < 4; mt++) {
#pragma unroll
        for (int nt = 0; nt < 4; nt++) {
#pragma unroll
            for (int half = 0; half < 2; half++) {
                int row = m0 + wmBase + mt * 16 + grp + half * 8;
                int col = n0 + wnBase + nt * 8 + 2 * tig;
                float v0 = acc[mt][nt][half * 2 + 0];
                float v1 = acc[mt][nt][half * 2 + 1];
                float y0, y1;
                if (mode == 0) {
                    y0 = v0 + bias[col]; y1 = v1 + bias[col + 1];
                } else {
                    float s0 = v0 / (1.0f + __expf(-v0));
                    float s1 = v1 / (1.0f + __expf(-v1));
                    const float2 cc = *(const float2*)(comp + (size_t)row * N + col);
                    y0 = cc.x * s0; y1 = cc.y * s1;
                }
                float2 o; o.x = y0; o.y = y1;
                *(float2*)(C + (size_t)row * N + col) = o;
            }
        }
    }
}

// ---------------- bf16 GEMM (R12-proven): fused alpha+delta ----------------
#define BKB 32

__global__ void __launch_bounds__(256, 2)
gemm_bf16_kernel(const __nv_bfloat16* __restrict__ Xb,
                 const __nv_bfloat16* __restrict__ Wa, const __nv_bfloat16* __restrict__ Wd,
                 const float* __restrict__ ba, const float* __restrict__ bd,
                 float* __restrict__ Ca, float* __restrict__ Cd)
{
    __shared__ uint32_t As[2][BM][LDW];
    __shared__ uint32_t Bs[2][BN][LDW];

    const int K = DIM, N = DIM;

    const int wsel = blockIdx.x >> 3;
    const int ntile = blockIdx.x & 7;
    const __nv_bfloat16* W = wsel ? Wd : Wa;
    const float* bias = wsel ? bd : ba;
    float* C = wsel ? Cd : Ca;

    const int tid  = threadIdx.x;
    const int lane = tid & 31;
    const int warp = tid >> 5;
    const int warpM = warp >> 2;   // 0..1
    const int warpN = warp & 3;    // 0..3
    const int wmBase = warpM * 64;
    const int wnBase = warpN * 32;

    const int m0 = blockIdx.y * BM;
    const int n0 = ntile * BN;

    const int ldRow = tid >> 2;           // 0..63
    const int ldCh  = (tid & 3);          // chunk 0..3
    const __nv_bfloat16* Aptr  = Xb + (size_t)(m0 + ldRow) * K + ldCh * 8;
    const __nv_bfloat16* Aptr2 = Aptr + (size_t)64 * K;
    const __nv_bfloat16* Wptr  = W + (size_t)(n0 + ldRow) * K + ldCh * 8;
    const __nv_bfloat16* Wptr2 = Wptr + (size_t)64 * K;

    const uint32_t AsBase = smem_u32(&As[0][0][0]);
    const uint32_t BsBase = smem_u32(&Bs[0][0][0]);

    const int lRow = (lane & 7) + ((lane >> 3) & 1) * 8;   // 0..15
    const int lKA  = (lane >> 4) * 16;                     // bytes
    const int bRowL = (lane & 7) + ((lane >> 4) << 3);     // 0..15
    const int lKB   = ((lane >> 3) & 1) * 16;              // bytes

    float acc[4][4][4];
#pragma unroll
    for (int i = 0; i < 4; i++)
#pragma unroll
        for (int j = 0; j < 4; j++)
#pragma unroll
            for (int r = 0; r < 4; r++) acc[i][j][r] = 0.f;

    const int grp = lane >> 2;
    const int tig = lane & 3;

    uint4 qa0 = *(const uint4*)(Aptr);
    uint4 qa1 = *(const uint4*)(Aptr2);
    uint4 qb0 = *(const uint4*)(Wptr);
    uint4 qb1 = *(const uint4*)(Wptr2);
    {
        *(uint4*)&As[0][ldRow][ldCh * 4]      = qa0;
        *(uint4*)&As[0][ldRow + 64][ldCh * 4] = qa1;
        *(uint4*)&Bs[0][ldRow][ldCh * 4]      = qb0;
        *(uint4*)&Bs[0][ldRow + 64][ldCh * 4] = qb1;
    }
    __syncthreads();

    int cur = 0;
    for (int k0 = 0; k0 < K; k0 += BKB) {
        const bool has_next = (k0 + BKB) < K;
        if (has_next) {
            int kn = k0 + BKB;
            qa0 = *(const uint4*)(Aptr  + kn);
            qa1 = *(const uint4*)(Aptr2 + kn);
            qb0 = *(const uint4*)(Wptr  + kn);
            qb1 = *(const uint4*)(Wptr2 + kn);
        }

        const uint32_t aRow = (uint32_t)(cur * BM + wmBase + lRow) * (LDW * 4);
        const uint32_t bRow = (uint32_t)(cur * BN + wnBase + bRowL) * (LDW * 4);
#pragma unroll
        for (int kk = 0; kk < 2; kk++) {
            const uint32_t kByte = (uint32_t)kk * 32;
            uint32_t af[4][4];
#pragma unroll
            for (int mt = 0; mt < 4; mt++) {
                uint32_t addr = AsBase + aRow + (uint32_t)(mt * 16) * (LDW * 4) + kByte + lKA;
                ldsm_x4(af[mt][0], af[mt][1], af[mt][2], af[mt][3], addr);
            }
            uint32_t bf[4][2];
#pragma unroll
            for (int pr = 0; pr < 2; pr++) {
                uint32_t addr = BsBase + bRow + (uint32_t)(pr * 16) * (LDW * 4) + kByte + lKB;
                ldsm_x4(bf[2 * pr][0], bf[2 * pr][1], bf[2 * pr + 1][0], bf[2 * pr + 1][1], addr);
            }
#pragma unroll
            for (int mt = 0; mt < 4; mt++)
#pragma unroll
                for (int nt = 0; nt < 4; nt++)
                    mma_bf16(acc[mt][nt], af[mt], bf[nt]);
        }

        if (has_next) {
            int nxt = cur ^ 1;
            *(uint4*)&As[nxt][ldRow][ldCh * 4]      = qa0;
            *(uint4*)&As[nxt][ldRow + 64][ldCh * 4] = qa1;
            *(uint4*)&Bs[nxt][ldRow][ldCh * 4]      = qb0;
            *(uint4*)&Bs[nxt][ldRow + 64][ldCh * 4] = qb1;
        }
        __syncthreads();
        cur ^= 1;
    }

#pragma unroll
    for (int mt = 0; mt < 4; mt++) {
#pragma unroll
        for (int nt = 0; nt < 4; nt++) {
#pragma unroll
            for (int half = 0; half < 2; half++) {
                int row = m0 + wmBase + mt * 16 + grp + half * 8;
                int col = n0 + wnBase + nt * 8 + 2 * tig;
                float x0 = acc[mt][nt][half * 2 + 0] + bias[col];
                float x1 = acc[mt][nt][half * 2 + 1] + bias[col + 1];
                float y0, y1;
                if (wsel == 0) {
                    y0 = 1.0f + ((x0 > 20.f) ? x0 : log1pf(__expf(x0)));
                    y1 = 1.0f + ((x1 > 20.f) ? x1 : log1pf(__expf(x1)));
                } else {
                    y0 = 1.0f / (1.0f + __expf(-x0));
                    y1 = 1.0f / (1.0f + __expf(-x1));
                }
                float2 o; o.x = y0; o.y = y1;
                *(float2*)(C + (size_t)row * N + col) = o;
            }
        }
    }
}

// ---------------- scan: recurrence, then BATCHED fused softmax ----------------
// 256 blocks x 64 threads; warp lanes = one (b,group).
// The 16 softmax chains per block are issued back-to-back (independent -> ILP),
// keeping the serial h-chain free of shfl latency.
__global__ void __launch_bounds__(64)
scan_kernel(const float* __restrict__ vx, const float* __restrict__ alpha,
            const float* __restrict__ delta, const float* __restrict__ h0,
            const float* __restrict__ r_h, float* __restrict__ out_h,
            float* __restrict__ cp)
{
    int gtid = blockIdx.x * 64 + threadIdx.x;   // 0..16383
    int b = gtid >> 10;
    int d = gtid & 1023;
    size_t base = (size_t)b * DIM + d;

    float rh = r_h[d];
    float h = h0[base];
    out_h[base] = h;

    float cv[16], ca[16], cd[16], nv[16], na[16], nd[16];
#pragma unroll
    for (int i = 0; i < 16; i++) {
        size_t o = (size_t)i * BD + base;
        cv[i] = __ldcs(vx + o); ca[i] = __ldcs(alpha + o); cd[i] = __ldcs(delta + o);
    }

    for (int t0 = 0; t0 < TT; t0 += 16) {
        const bool more = (t0 + 16) < TT;
        if (more) {
#pragma unroll
            for (int i = 0; i < 16; i++) {
                size_t o = (size_t)(t0 + 16 + i) * BD + base;
                nv[i] = __ldcs(vx + o); na[i] = __ldcs(alpha + o); nd[i] = __ldcs(delta + o);
            }
        }

        // ---- pure recurrence chain (no shfl on this path) ----
        float hr[16];
#pragma unroll
        for (int i = 0; i < 16; i++) {
            float v = cv[i] + rh * h;
            float av = fminf(fmaxf(fabsf(v), 1e-6f), 10.0f);
            float cand = __powf(av, ca[i]);
            cand = (v >= 0.f) ? cand : -cand;
            if (v == 0.f) cand = 0.f;     // jnp.sign(0) == 0
            h = h + cd[i] * (cand - h);
            hr[i] = h;
        }

        // ---- batched store + softmax: 16 independent chains overlap ----
#pragma unroll
        for (int i = 0; i < 16; i++) {
            size_t o = (size_t)(t0 + i) * BD + base;
            __stcs(out_h + o + BD, hr[i]);
            float m = hr[i];
#pragma unroll
            for (int of = 16; of > 0; of >>= 1) m = fmaxf(m, __shfl_xor_sync(0xffffffffu, m, of));
            float e = __expf(hr[i] - m);
            float s = e;
#pragma unroll
            for (int of = 16; of > 0; of >>= 1) s += __shfl_xor_sync(0xffffffffu, s, of);
            __stcs(cp + o, e / s);
        }

        if (more) {
#pragma unroll
            for (int i = 0; i < 16; i++) { cv[i] = nv[i]; ca[i] = na[i]; cd[i] = nd[i]; }
        }
    }
}

// ---------------- launch ----------------
extern "C" void kernel_launch(void* const* d_in, const int* in_sizes, int n_in,
                              void* d_out, int out_size)
{
    const float* x       = (const float*)d_in[0];   // [T,B,D]
    const float* h0      = (const float*)d_in[1];   // [B,D]
    const float* W_x     = (const float*)d_in[2];   // [D,D]
    const float* r_h     = (const float*)d_in[3];   // [D]
    const float* b       = (const float*)d_in[4];   // [D]
    const float* W_alpha = (const float*)d_in[5];
    const float* b_alpha = (const float*)d_in[6];
    const float* W_delta = (const float*)d_in[7];
    const float* b_delta = (const float*)d_in[8];
    const float* W_out   = (const float*)d_in[9];

    float* out = (float*)d_out;
    float* out_h = out;                                  // [T+1,B,D]
    float* out_y = out + (size_t)(TT + 1) * BD;          // [T,B,D]

    float *vx, *al, *dl, *cpt;
    __nv_bfloat16 *xb, *wab, *wdb;
    cudaGetSymbolAddress((void**)&vx, g_vx);
    cudaGetSymbolAddress((void**)&al, g_alpha);
    cudaGetSymbolAddress((void**)&dl, g_delta);
    cudaGetSymbolAddress((void**)&cpt, g_compete);
    cudaGetSymbolAddress((void**)&xb, g_xb);
    cudaGetSymbolAddress((void**)&wab, g_wab);
    cudaGetSymbolAddress((void**)&wdb, g_wdb);

    // 0) bf16 converts for the alpha/delta path
    const int XN8 = MROWS * DIM / 8;                     // 2M
    const int WN8 = DIM * DIM / 8;                       // 131072
    bf16_convert_kernel<<<(XN8 + 255) / 256, 256>>>(x, xb, XN8);
    bf16_convert_kernel<<<(WN8 + 255) / 256, 256>>>(W_alpha, wab, WN8);
    bf16_convert_kernel<<<(WN8 + 255) / 256, 256>>>(W_delta, wdb, WN8);

    // 1) vx projection (tf32)
    dim3 vgrid(DIM / BN, MROWS / BM);          // (8, 128)
    gemm_tf32_kernel<<<vgrid, 256>>>(x, W_x, b, nullptr, vx, 0);

    // 2) alpha + delta projections (bf16)
    dim3 agrid(2 * (DIM / BN), MROWS / BM);    // (16, 128)
    gemm_bf16_kernel<<<agrid, 256>>>(xb, wab, wdb, b_alpha, b_delta, al, dl);

    // 3) sequential scan + batched fused compete softmax
    scan_kernel<<<256, 64>>>(vx, al, dl, h0, r_h, out_h, cpt);

    // 4) output GEMM with compete*silu epilogue (tf32)
    gemm_tf32_kernel<<<vgrid, 256>>>(out_h + BD, W_out, nullptr, cpt, out_y, 3);
}

// round 15
// speedup vs baseline: 1.7012x; 1.0296x over previous
#include <cuda_runtime.h>
#include <cuda_bf16.h>
#include <cstdint>

#define DIM 1024
#define NGROUPS 32
#define GSIZE 32
#define TT 1024
#define BB 16
#define MROWS (TT * BB)          // 16384
#define BD (BB * DIM)            // 16384

// ---------------- scratch (device globals; no allocation allowed) ----------------
__device__ float g_vx[MROWS * DIM];
__device__ float g_alpha[MROWS * DIM];
__device__ float g_delta[MROWS * DIM];
__device__ float g_compete[MROWS * DIM];
__device__ __nv_bfloat16 g_xb[MROWS * DIM];      // bf16 x
__device__ __nv_bfloat16 g_wab[DIM * DIM];       // bf16 W_alpha
__device__ __nv_bfloat16 g_wdb[DIM * DIM];       // bf16 W_delta
__device__ int g_rhflag[1];                      // 1 if any r_h != 0

// ---------------- helpers ----------------
__device__ __forceinline__ uint32_t f2tf32(float x) {
    uint32_t r;
    asm("cvt.rna.tf32.f32 %0, %1;" : "=r"(r) : "f"(x));
    return r;
}

__device__ __forceinline__ uint32_t pack_bf16x2(float lo, float hi) {
    uint32_t r;
    asm("cvt.rn.bf16x2.f32 %0, %1, %2;" : "=r"(r) : "f"(hi), "f"(lo));
    return r;
}

__device__ __forceinline__ void mma_tf32(float* c, const uint32_t* a, const uint32_t* b) {
    asm volatile(
        "mma.sync.aligned.m16n8k8.row.col.f32.tf32.tf32.f32 "
        "{%0,%1,%2,%3}, {%4,%5,%6,%7}, {%8,%9}, {%0,%1,%2,%3};"
        : "+f"(c[0]), "+f"(c[1]), "+f"(c[2]), "+f"(c[3])
        : "r"(a[0]), "r"(a[1]), "r"(a[2]), "r"(a[3]), "r"(b[0]), "r"(b[1]));
}

__device__ __forceinline__ void mma_bf16(float* c, const uint32_t* a, const uint32_t* b) {
    asm volatile(
        "mma.sync.aligned.m16n8k16.row.col.f32.bf16.bf16.f32 "
        "{%0,%1,%2,%3}, {%4,%5,%6,%7}, {%8,%9}, {%0,%1,%2,%3};"
        : "+f"(c[0]), "+f"(c[1]), "+f"(c[2]), "+f"(c[3])
        : "r"(a[0]), "r"(a[1]), "r"(a[2]), "r"(a[3]), "r"(b[0]), "r"(b[1]));
}

__device__ __forceinline__ void ldsm_x4(uint32_t& r0, uint32_t& r1, uint32_t& r2, uint32_t& r3,
                                        uint32_t addr) {
    asm volatile("ldmatrix.sync.aligned.m8n8.x4.shared.b16 {%0,%1,%2,%3}, [%4];"
                 : "=r"(r0), "=r"(r1), "=r"(r2), "=r"(r3) : "r"(addr));
}

__device__ __forceinline__ uint32_t smem_u32(const void* p) {
    uint32_t a;
    asm("{ .reg .u64 t; cvta.to.shared.u64 t, %1; cvt.u32.u64 %0, t; }" : "=r"(a) : "l"(p));
    return a;
}

// ---------------- bf16 convert (8 floats per thread) ----------------
__global__ void __launch_bounds__(256)
bf16_convert_kernel(const float* __restrict__ in, __nv_bfloat16* __restrict__ out, int n8)
{
    int i = blockIdx.x * blockDim.x + threadIdx.x;
    if (i < n8) {
        float4 a = ((const float4*)in)[2 * i];
        float4 c = ((const float4*)in)[2 * i + 1];
        uint4 o;
        o.x = pack_bf16x2(a.x, a.y); o.y = pack_bf16x2(a.z, a.w);
        o.z = pack_bf16x2(c.x, c.y); o.w = pack_bf16x2(c.z, c.w);
        ((uint4*)out)[i] = o;
    }
}

// ---------------- r_h zero-detect flag ----------------
__global__ void __launch_bounds__(256)
rh_flag_kernel(const float* __restrict__ rh, int* __restrict__ flag)
{
    __shared__ int any;
    if (threadIdx.x == 0) any = 0;
    __syncthreads();
    int local = 0;
    for (int i = threadIdx.x; i < DIM; i += 256)
        local |= (rh[i] != 0.0f);
    if (local) atomicOr(&any, 1);
    __syncthreads();
    if (threadIdx.x == 0) *flag = any;
}

#define BM 128
#define BN 128
#define LDW 20    // smem row stride in words (80B): proven conflict-free

// ---------------- tf32 GEMM (proven body): C = A @ W^T, epilogue by mode ----
// mode 0: y = acc + bias;  mode 3: y = compete * silu(acc)
__global__ void __launch_bounds__(256, 2)
gemm_tf32_kernel(const float* __restrict__ A, const float* __restrict__ W,
                 const float* __restrict__ bias, const float* __restrict__ comp,
                 float* __restrict__ C, int mode)
{
    __shared__ uint32_t As[2][BM][LDW];
    __shared__ uint32_t Bs[2][BN][LDW];

    const int K = DIM, N = DIM;
    const int tid  = threadIdx.x;
    const int lane = tid & 31;
    const int warp = tid >> 5;
    const int warpM = warp >> 2;   // 0..1
    const int warpN = warp & 3;    // 0..3
    const int wmBase = warpM * 64;
    const int wnBase = warpN * 32;

    const int m0 = blockIdx.y * BM;
    const int n0 = blockIdx.x * BN;

    const int ldRow = tid >> 2;
    const int ldCol = (tid & 3) * 4;

    const float* Aptr  = A + (size_t)(m0 + ldRow) * K + ldCol;
    const float* Aptr2 = Aptr + (size_t)64 * K;
    const float* Wptr  = W + (size_t)(n0 + ldRow) * K + ldCol;
    const float* Wptr2 = Wptr + (size_t)64 * K;

    const int lRow = (lane & 7) + ((lane >> 3) & 1) * 8;  // 0..15
    const int lK   = (lane >> 4) * 4;                     // 0 or 4

    const uint32_t AsBase = smem_u32(&As[0][0][0]);
    const uint32_t BsBase = smem_u32(&Bs[0][0][0]);

    float acc[4][4][4];
#pragma unroll
    for (int i = 0; i < 4; i++)
#pragma unroll
        for (int j = 0; j < 4; j++)
#pragma unroll
            for (int r = 0; r < 4; r++) acc[i][j][r] = 0.f;

    const int grp = lane >> 2;
    const int tig = lane & 3;

    float4 ra0 = *(const float4*)(Aptr);
    float4 ra1 = *(const float4*)(Aptr2);
    float4 rb0 = *(const float4*)(Wptr);
    float4 rb1 = *(const float4*)(Wptr2);
    {
        uint4 v;
        v.x = f2tf32(ra0.x); v.y = f2tf32(ra0.y); v.z = f2tf32(ra0.z); v.w = f2tf32(ra0.w);
        *(uint4*)&As[0][ldRow][ldCol] = v;
        v.x = f2tf32(ra1.x); v.y = f2tf32(ra1.y); v.z = f2tf32(ra1.z); v.w = f2tf32(ra1.w);
        *(uint4*)&As[0][ldRow + 64][ldCol] = v;
        v.x = f2tf32(rb0.x); v.y = f2tf32(rb0.y); v.z = f2tf32(rb0.z); v.w = f2tf32(rb0.w);
        *(uint4*)&Bs[0][ldRow][ldCol] = v;
        v.x = f2tf32(rb1.x); v.y = f2tf32(rb1.y); v.z = f2tf32(rb1.z); v.w = f2tf32(rb1.w);
        *(uint4*)&Bs[0][ldRow + 64][ldCol] = v;
    }
    __syncthreads();

    int cur = 0;
    for (int k0 = 0; k0 < K; k0 += 16) {
        const bool has_next = (k0 + 16) < K;
        if (has_next) {
            int kn = k0 + 16;
            ra0 = *(const float4*)(Aptr  + kn);
            ra1 = *(const float4*)(Aptr2 + kn);
            rb0 = *(const float4*)(Wptr  + kn);
            rb1 = *(const float4*)(Wptr2 + kn);
        }

        const uint32_t aRow = (uint32_t)(cur * BM + wmBase + lRow) * (LDW * 4);
        const uint32_t bRow = (uint32_t)(cur * BN + wnBase + lRow) * (LDW * 4);
#pragma unroll
        for (int kk = 0; kk < 16; kk += 8) {
            const uint32_t kOff = (uint32_t)(kk + lK) * 4;
            uint32_t af[4][4];
#pragma unroll
            for (int mt = 0; mt < 4; mt++) {
                uint32_t addr = AsBase + aRow + (uint32_t)(mt * 16) * (LDW * 4) + kOff;
                ldsm_x4(af[mt][0], af[mt][1], af[mt][2], af[mt][3], addr);
            }
            uint32_t bf[4][2];
#pragma unroll
            for (int pr = 0; pr < 2; pr++) {
                uint32_t addr = BsBase + bRow + (uint32_t)(pr * 16) * (LDW * 4) + kOff;
                ldsm_x4(bf[2 * pr][0], bf[2 * pr + 1][0], bf[2 * pr][1], bf[2 * pr + 1][1], addr);
            }
#pragma unroll
            for (int mt = 0; mt < 4; mt++)
#pragma unroll
                for (int nt = 0; nt < 4; nt++)
                    mma_tf32(acc[mt][nt], af[mt], bf[nt]);
        }

        if (has_next) {
            int nxt = cur ^ 1;
            uint4 v;
            v.x = f2tf32(ra0.x); v.y = f2tf32(ra0.y); v.z = f2tf32(ra0.z); v.w = f2tf32(ra0.w);
            *(uint4*)&As[nxt][ldRow][ldCol] = v;
            v.x = f2tf32(ra1.x); v.y = f2tf32(ra1.y); v.z = f2tf32(ra1.z); v.w = f2tf32(ra1.w);
            *(uint4*)&As[nxt][ldRow + 64][ldCol] = v;
            v.x = f2tf32(rb0.x); v.y = f2tf32(rb0.y); v.z = f2tf32(rb0.z); v.w = f2tf32(rb0.w);
            *(uint4*)&Bs[nxt][ldRow][ldCol] = v;
            v.x = f2tf32(rb1.x); v.y = f2tf32(rb1.y); v.z = f2tf32(rb1.z); v.w = f2tf32(rb1.w);
            *(uint4*)&Bs[nxt][ldRow + 64][ldCol] = v;
        }
        __syncthreads();
        cur ^= 1;
    }

#pragma unroll
    for (int mt = 0; mt < 4; mt++) {
#pragma unroll
        for (int nt = 0; nt < 4; nt++) {
#pragma unroll
            for (int half = 0; half < 2; half++) {
                int row = m0 + wmBase + mt * 16 + grp + half * 8;
                int col = n0 + wnBase + nt * 8 + 2 * tig;
                float v0 = acc[mt][nt][half * 2 + 0];
                float v1 = acc[mt][nt][half * 2 + 1];
                float y0, y1;
                if (mode == 0) {
                    y0 = v0 + bias[col]; y1 = v1 + bias[col + 1];
                } else {
                    float s0 = v0 / (1.0f + __expf(-v0));
                    float s1 = v1 / (1.0f + __expf(-v1));
                    const float2 cc = *(const float2*)(comp + (size_t)row * N + col);
                    y0 = cc.x * s0; y1 = cc.y * s1;
                }
                float2 o; o.x = y0; o.y = y1;
                *(float2*)(C + (size_t)row * N + col) = o;
            }
        }
    }
}

// ---------------- bf16 GEMM (R12-proven): fused alpha+delta ----------------
#define BKB 32

__global__ void __launch_bounds__(256, 2)
gemm_bf16_kernel(const __nv_bfloat16* __restrict__ Xb,
                 const __nv_bfloat16* __restrict__ Wa, const __nv_bfloat16* __restrict__ Wd,
                 const float* __restrict__ ba, const float* __restrict__ bd,
                 float* __restrict__ Ca, float* __restrict__ Cd)
{
    __shared__ uint32_t As[2][BM][LDW];
    __shared__ uint32_t Bs[2][BN][LDW];

    const int K = DIM, N = DIM;

    const int wsel = blockIdx.x >> 3;
    const int ntile = blockIdx.x & 7;
    const __nv_bfloat16* W = wsel ? Wd : Wa;
    const float* bias = wsel ? bd : ba;
    float* C = wsel ? Cd : Ca;

    const int tid  = threadIdx.x;
    const int lane = tid & 31;
    const int warp = tid >> 5;
    const int warpM = warp >> 2;   // 0..1
    const int warpN = warp & 3;    // 0..3
    const int wmBase = warpM * 64;
    const int wnBase = warpN * 32;

    const int m0 = blockIdx.y * BM;
    const int n0 = ntile * BN;

    const int ldRow = tid >> 2;           // 0..63
    const int ldCh  = (tid & 3);          // chunk 0..3
    const __nv_bfloat16* Aptr  = Xb + (size_t)(m0 + ldRow) * K + ldCh * 8;
    const __nv_bfloat16* Aptr2 = Aptr + (size_t)64 * K;
    const __nv_bfloat16* Wptr  = W + (size_t)(n0 + ldRow) * K + ldCh * 8;
    const __nv_bfloat16* Wptr2 = Wptr + (size_t)64 * K;

    const uint32_t AsBase = smem_u32(&As[0][0][0]);
    const uint32_t BsBase = smem_u32(&Bs[0][0][0]);

    const int lRow = (lane & 7) + ((lane >> 3) & 1) * 8;   // 0..15
    const int lKA  = (lane >> 4) * 16;                     // bytes
    const int bRowL = (lane & 7) + ((lane >> 4) << 3);     // 0..15
    const int lKB   = ((lane >> 3) & 1) * 16;              // bytes

    float acc[4][4][4];
#pragma unroll
    for (int i = 0; i < 4; i++)
#pragma unroll
        for (int j = 0; j < 4; j++)
#pragma unroll
            for (int r = 0; r < 4; r++) acc[i][j][r] = 0.f;

    const int grp = lane >> 2;
    const int tig = lane & 3;

    uint4 qa0 = *(const uint4*)(Aptr);
    uint4 qa1 = *(const uint4*)(Aptr2);
    uint4 qb0 = *(const uint4*)(Wptr);
    uint4 qb1 = *(const uint4*)(Wptr2);
    {
        *(uint4*)&As[0][ldRow][ldCh * 4]      = qa0;
        *(uint4*)&As[0][ldRow + 64][ldCh * 4] = qa1;
        *(uint4*)&Bs[0][ldRow][ldCh * 4]      = qb0;
        *(uint4*)&Bs[0][ldRow + 64][ldCh * 4] = qb1;
    }
    __syncthreads();

    int cur = 0;
    for (int k0 = 0; k0 < K; k0 += BKB) {
        const bool has_next = (k0 + BKB) < K;
        if (has_next) {
            int kn = k0 + BKB;
            qa0 = *(const uint4*)(Aptr  + kn);
            qa1 = *(const uint4*)(Aptr2 + kn);
            qb0 = *(const uint4*)(Wptr  + kn);
            qb1 = *(const uint4*)(Wptr2 + kn);
        }

        const uint32_t aRow = (uint32_t)(cur * BM + wmBase + lRow) * (LDW * 4);
        const uint32_t bRow = (uint32_t)(cur * BN + wnBase + bRowL) * (LDW * 4);
#pragma unroll
        for (int kk = 0; kk < 2; kk++) {
            const uint32_t kByte = (uint32_t)kk * 32;
            uint32_t af[4][4];
#pragma unroll
            for (int mt = 0; mt < 4; mt++) {
                uint32_t addr = AsBase + aRow + (uint32_t)(mt * 16) * (LDW * 4) + kByte + lKA;
                ldsm_x4(af[mt][0], af[mt][1], af[mt][2], af[mt][3], addr);
            }
            uint32_t bf[4][2];
#pragma unroll
            for (int pr = 0; pr < 2; pr++) {
                uint32_t addr = BsBase + bRow + (uint32_t)(pr * 16) * (LDW * 4) + kByte + lKB;
                ldsm_x4(bf[2 * pr][0], bf[2 * pr][1], bf[2 * pr + 1][0], bf[2 * pr + 1][1], addr);
            }
#pragma unroll
            for (int mt = 0; mt < 4; mt++)
#pragma unroll
                for (int nt = 0; nt < 4; nt++)
                    mma_bf16(acc[mt][nt], af[mt], bf[nt]);
        }

        if (has_next) {
            int nxt = cur ^ 1;
            *(uint4*)&As[nxt][ldRow][ldCh * 4]      = qa0;
            *(uint4*)&As[nxt][ldRow + 64][ldCh * 4] = qa1;
            *(uint4*)&Bs[nxt][ldRow][ldCh * 4]      = qb0;
            *(uint4*)&Bs[nxt][ldRow + 64][ldCh * 4] = qb1;
        }
        __syncthreads();
        cur ^= 1;
    }

#pragma unroll
    for (int mt = 0; mt < 4; mt++) {
#pragma unroll
        for (int nt = 0; nt < 4; nt++) {
#pragma unroll
            for (int half = 0; half < 2; half++) {
                int row = m0 + wmBase + mt * 16 + grp + half * 8;
                int col = n0 + wnBase + nt * 8 + 2 * tig;
                float x0 = acc[mt][nt][half * 2 + 0] + bias[col];
                float x1 = acc[mt][nt][half * 2 + 1] + bias[col + 1];
                float y0, y1;
                if (wsel == 0) {
                    y0 = 1.0f + ((x0 > 20.f) ? x0 : log1pf(__expf(x0)));
                    y1 = 1.0f + ((x1 > 20.f) ? x1 : log1pf(__expf(x1)));
                } else {
                    y0 = 1.0f / (1.0f + __expf(-x0));
                    y1 = 1.0f / (1.0f + __expf(-x1));
                }
                float2 o; o.x = y0; o.y = y1;
                *(float2*)(C + (size_t)row * N + col) = o;
            }
        }
    }
}

// ---------------- scan: recurrence + batched softmax; fast path when r_h == 0 ----
// 256 blocks x 64 threads; warp lanes = one (b,group).
// flag==0 (r_h all zero): cand is h-independent -> computed with full ILP; the
// recurrence collapses to a single-FMA chain (~8 cyc/step vs ~60).
__global__ void __launch_bounds__(64)
scan_kernel(const float* __restrict__ vx, const float* __restrict__ alpha,
            const float* __restrict__ delta, const float* __restrict__ h0,
            const float* __restrict__ r_h, float* __restrict__ out_h,
            float* __restrict__ cp, const int* __restrict__ rhflag)
{
    int gtid = blockIdx.x * 64 + threadIdx.x;   // 0..16383
    int b = gtid >> 10;
    int d = gtid & 1023;
    size_t base = (size_t)b * DIM + d;

    const bool fast = (*rhflag == 0);
    float rh = r_h[d];
    float h = h0[base];
    out_h[base] = h;

    float cv[16], ca[16], cd[16], nv[16], na[16], nd[16];
#pragma unroll
    for (int i = 0; i < 16; i++) {
        size_t o = (size_t)i * BD + base;
        cv[i] = __ldcs(vx + o); ca[i] = __ldcs(alpha + o); cd[i] = __ldcs(delta + o);
    }

    for (int t0 = 0; t0 < TT; t0 += 16) {
        const bool more = (t0 + 16) < TT;
        if (more) {
#pragma unroll
            for (int i = 0; i < 16; i++) {
                size_t o = (size_t)(t0 + 16 + i) * BD + base;
                nv[i] = __ldcs(vx + o); na[i] = __ldcs(alpha + o); nd[i] = __ldcs(delta + o);
            }
        }

        float hr[16];
        if (fast) {
            // cand independent of h: full ILP over 16 steps (MUFU chains overlap)
            float cand[16];
#pragma unroll
            for (int i = 0; i < 16; i++) {
                float v = cv[i];                 // + 0*h exactly
                float av = fminf(fmaxf(fabsf(v), 1e-6f), 10.0f);
                float c = __powf(av, ca[i]);
                c = (v >= 0.f) ? c : -c;
                if (v == 0.f) c = 0.f;
                cand[i] = c;
            }
            // single-FMA recurrence chain
#pragma unroll
            for (int i = 0; i < 16; i++) {
                h = h + cd[i] * (cand[i] - h);
                hr[i] = h;
            }
        } else {
            // general path (identical to R13)
#pragma unroll
            for (int i = 0; i < 16; i++) {
                float v = cv[i] + rh * h;
                float av = fminf(fmaxf(fabsf(v), 1e-6f), 10.0f);
                float cand = __powf(av, ca[i]);
                cand = (v >= 0.f) ? cand : -cand;
                if (v == 0.f) cand = 0.f;
                h = h + cd[i] * (cand - h);
                hr[i] = h;
            }
        }

        // batched store + softmax: 16 independent chains overlap
#pragma unroll
        for (int i = 0; i < 16; i++) {
            size_t o = (size_t)(t0 + i) * BD + base;
            __stcs(out_h + o + BD, hr[i]);
            float m = hr[i];
#pragma unroll
            for (int of = 16; of > 0; of >>= 1) m = fmaxf(m, __shfl_xor_sync(0xffffffffu, m, of));
            float e = __expf(hr[i] - m);
            float s = e;
#pragma unroll
            for (int of = 16; of > 0; of >>= 1) s += __shfl_xor_sync(0xffffffffu, s, of);
            __stcs(cp + o, e / s);
        }

        if (more) {
#pragma unroll
            for (int i = 0; i < 16; i++) { cv[i] = nv[i]; ca[i] = na[i]; cd[i] = nd[i]; }
        }
    }
}

// ---------------- launch ----------------
extern "C" void kernel_launch(void* const* d_in, const int* in_sizes, int n_in,
                              void* d_out, int out_size)
{
    const float* x       = (const float*)d_in[0];   // [T,B,D]
    const float* h0      = (const float*)d_in[1];   // [B,D]
    const float* W_x     = (const float*)d_in[2];   // [D,D]
    const float* r_h     = (const float*)d_in[3];   // [D]
    const float* b       = (const float*)d_in[4];   // [D]
    const float* W_alpha = (const float*)d_in[5];
    const float* b_alpha = (const float*)d_in[6];
    const float* W_delta = (const float*)d_in[7];
    const float* b_delta = (const float*)d_in[8];
    const float* W_out   = (const float*)d_in[9];

    float* out = (float*)d_out;
    float* out_h = out;                                  // [T+1,B,D]
    float* out_y = out + (size_t)(TT + 1) * BD;          // [T,B,D]

    float *vx, *al, *dl, *cpt;
    __nv_bfloat16 *xb, *wab, *wdb;
    int* rhf;
    cudaGetSymbolAddress((void**)&vx, g_vx);
    cudaGetSymbolAddress((void**)&al, g_alpha);
    cudaGetSymbolAddress((void**)&dl, g_delta);
    cudaGetSymbolAddress((void**)&cpt, g_compete);
    cudaGetSymbolAddress((void**)&xb, g_xb);
    cudaGetSymbolAddress((void**)&wab, g_wab);
    cudaGetSymbolAddress((void**)&wdb, g_wdb);
    cudaGetSymbolAddress((void**)&rhf, g_rhflag);

    // 0) r_h flag + bf16 converts
    rh_flag_kernel<<<1, 256>>>(r_h, rhf);
    const int XN8 = MROWS * DIM / 8;                     // 2M
    const int WN8 = DIM * DIM / 8;                       // 131072
    bf16_convert_kernel<<<(XN8 + 255) / 256, 256>>>(x, xb, XN8);
    bf16_convert_kernel<<<(WN8 + 255) / 256, 256>>>(W_alpha, wab, WN8);
    bf16_convert_kernel<<<(WN8 + 255) / 256, 256>>>(W_delta, wdb, WN8);

    // 1) vx projection (tf32)
    dim3 vgrid(DIM / BN, MROWS / BM);          // (8, 128)
    gemm_tf32_kernel<<<vgrid, 256>>>(x, W_x, b, nullptr, vx, 0);

    // 2) alpha + delta projections (bf16)
    dim3 agrid(2 * (DIM / BN), MROWS / BM);    // (16, 128)
    gemm_bf16_kernel<<<agrid, 256>>>(xb, wab, wdb, b_alpha, b_delta, al, dl);

    // 3) sequential scan + batched fused compete softmax (fast path if r_h==0)
    scan_kernel<<<256, 64>>>(vx, al, dl, h0, r_h, out_h, cpt, rhf);

    // 4) output GEMM with compete*silu epilogue (tf32)
    gemm_tf32_kernel<<<vgrid, 256>>>(out_h + BD, W_out, nullptr, cpt, out_y, 3);
}

// round 16
// speedup vs baseline: 1.8641x; 1.0957x over previous
#include <cuda_runtime.h>
#include <cuda_bf16.h>
#include <cstdint>

#define DIM 1024
#define NGROUPS 32
#define GSIZE 32
#define TT 1024
#define BB 16
#define MROWS (TT * BB)          // 16384
#define BD (BB * DIM)            // 16384
#define NCH 8
#define CHL (TT / NCH)           // 128

// ---------------- scratch (device globals; no allocation allowed) ----------------
__device__ float g_vx[MROWS * DIM];
__device__ float g_alpha[MROWS * DIM];
__device__ float g_delta[MROWS * DIM];
__device__ float g_compete[MROWS * DIM];
__device__ __nv_bfloat16 g_xb[MROWS * DIM];      // bf16 x
__device__ __nv_bfloat16 g_wab[DIM * DIM];       // bf16 W_alpha
__device__ __nv_bfloat16 g_wdb[DIM * DIM];       // bf16 W_delta
__device__ int g_rhflag[1];                      // 1 if any r_h != 0
__device__ float g_chA[NCH * BD];                // per-chunk A
__device__ float g_chB[NCH * BD];                // per-chunk B
__device__ float g_hstart[NCH * BD];             // per-chunk start h

// ---------------- helpers ----------------
__device__ __forceinline__ uint32_t f2tf32(float x) {
    uint32_t r;
    asm("cvt.rna.tf32.f32 %0, %1;" : "=r"(r) : "f"(x));
    return r;
}

__device__ __forceinline__ uint32_t pack_bf16x2(float lo, float hi) {
    uint32_t r;
    asm("cvt.rn.bf16x2.f32 %0, %1, %2;" : "=r"(r) : "f"(hi), "f"(lo));
    return r;
}

__device__ __forceinline__ void mma_tf32(float* c, const uint32_t* a, const uint32_t* b) {
    asm volatile(
        "mma.sync.aligned.m16n8k8.row.col.f32.tf32.tf32.f32 "
        "{%0,%1,%2,%3}, {%4,%5,%6,%7}, {%8,%9}, {%0,%1,%2,%3};"
        : "+f"(c[0]), "+f"(c[1]), "+f"(c[2]), "+f"(c[3])
        : "r"(a[0]), "r"(a[1]), "r"(a[2]), "r"(a[3]), "r"(b[0]), "r"(b[1]));
}

__device__ __forceinline__ void mma_bf16(float* c, const uint32_t* a, const uint32_t* b) {
    asm volatile(
        "mma.sync.aligned.m16n8k16.row.col.f32.bf16.bf16.f32 "
        "{%0,%1,%2,%3}, {%4,%5,%6,%7}, {%8,%9}, {%0,%1,%2,%3};"
        : "+f"(c[0]), "+f"(c[1]), "+f"(c[2]), "+f"(c[3])
        : "r"(a[0]), "r"(a[1]), "r"(a[2]), "r"(a[3]), "r"(b[0]), "r"(b[1]));
}

__device__ __forceinline__ void ldsm_x4(uint32_t& r0, uint32_t& r1, uint32_t& r2, uint32_t& r3,
                                        uint32_t addr) {
    asm volatile("ldmatrix.sync.aligned.m8n8.x4.shared.b16 {%0,%1,%2,%3}, [%4];"
                 : "=r"(r0), "=r"(r1), "=r"(r2), "=r"(r3) : "r"(addr));
}

__device__ __forceinline__ uint32_t smem_u32(const void* p) {
    uint32_t a;
    asm("{ .reg .u64 t; cvta.to.shared.u64 t, %1; cvt.u32.u64 %0, t; }" : "=r"(a) : "l"(p));
    return a;
}

// candidate = sign(v) * clip(|v|,1e-6,10)^a   (jnp.sign(0)=0)
__device__ __forceinline__ float cand_fn(float v, float a) {
    float av = fminf(fmaxf(fabsf(v), 1e-6f), 10.0f);
    float c = __powf(av, a);
    c = (v >= 0.f) ? c : -c;
    if (v == 0.f) c = 0.f;
    return c;
}

// ---------------- bf16 convert (8 floats per thread) ----------------
__global__ void __launch_bounds__(256)
bf16_convert_kernel(const float* __restrict__ in, __nv_bfloat16* __restrict__ out, int n8)
{
    int i = blockIdx.x * blockDim.x + threadIdx.x;
    if (i < n8) {
        float4 a = ((const float4*)in)[2 * i];
        float4 c = ((const float4*)in)[2 * i + 1];
        uint4 o;
        o.x = pack_bf16x2(a.x, a.y); o.y = pack_bf16x2(a.z, a.w);
        o.z = pack_bf16x2(c.x, c.y); o.w = pack_bf16x2(c.z, c.w);
        ((uint4*)out)[i] = o;
    }
}

// ---------------- r_h zero-detect flag ----------------
__global__ void __launch_bounds__(256)
rh_flag_kernel(const float* __restrict__ rh, int* __restrict__ flag)
{
    __shared__ int any;
    if (threadIdx.x == 0) any = 0;
    __syncthreads();
    int local = 0;
    for (int i = threadIdx.x; i < DIM; i += 256)
        local |= (rh[i] != 0.0f);
    if (local) atomicOr(&any, 1);
    __syncthreads();
    if (threadIdx.x == 0) *flag = any;
}

#define BM 128
#define BN 128
#define LDW 20    // smem row stride in words (80B): proven conflict-free

// ---------------- tf32 GEMM (proven body): C = A @ W^T, epilogue by mode ----
__global__ void __launch_bounds__(256, 2)
gemm_tf32_kernel(const float* __restrict__ A, const float* __restrict__ W,
                 const float* __restrict__ bias, const float* __restrict__ comp,
                 float* __restrict__ C, int mode)
{
    __shared__ uint32_t As[2][BM][LDW];
    __shared__ uint32_t Bs[2][BN][LDW];

    const int K = DIM, N = DIM;
    const int tid  = threadIdx.x;
    const int lane = tid & 31;
    const int warp = tid >> 5;
    const int warpM = warp >> 2;
    const int warpN = warp & 3;
    const int wmBase = warpM * 64;
    const int wnBase = warpN * 32;

    const int m0 = blockIdx.y * BM;
    const int n0 = blockIdx.x * BN;

    const int ldRow = tid >> 2;
    const int ldCol = (tid & 3) * 4;

    const float* Aptr  = A + (size_t)(m0 + ldRow) * K + ldCol;
    const float* Aptr2 = Aptr + (size_t)64 * K;
    const float* Wptr  = W + (size_t)(n0 + ldRow) * K + ldCol;
    const float* Wptr2 = Wptr + (size_t)64 * K;

    const int lRow = (lane & 7) + ((lane >> 3) & 1) * 8;
    const int lK   = (lane >> 4) * 4;

    const uint32_t AsBase = smem_u32(&As[0][0][0]);
    const uint32_t BsBase = smem_u32(&Bs[0][0][0]);

    float acc[4][4][4];
#pragma unroll
    for (int i = 0; i < 4; i++)
#pragma unroll
        for (int j = 0; j < 4; j++)
#pragma unroll
            for (int r = 0; r < 4; r++) acc[i][j][r] = 0.f;

    const int grp = lane >> 2;
    const int tig = lane & 3;

    float4 ra0 = *(const float4*)(Aptr);
    float4 ra1 = *(const float4*)(Aptr2);
    float4 rb0 = *(const float4*)(Wptr);
    float4 rb1 = *(const float4*)(Wptr2);
    {
        uint4 v;
        v.x = f2tf32(ra0.x); v.y = f2tf32(ra0.y); v.z = f2tf32(ra0.z); v.w = f2tf32(ra0.w);
        *(uint4*)&As[0][ldRow][ldCol] = v;
        v.x = f2tf32(ra1.x); v.y = f2tf32(ra1.y); v.z = f2tf32(ra1.z); v.w = f2tf32(ra1.w);
        *(uint4*)&As[0][ldRow + 64][ldCol] = v;
        v.x = f2tf32(rb0.x); v.y = f2tf32(rb0.y); v.z = f2tf32(rb0.z); v.w = f2tf32(rb0.w);
        *(uint4*)&Bs[0][ldRow][ldCol] = v;
        v.x = f2tf32(rb1.x); v.y = f2tf32(rb1.y); v.z = f2tf32(rb1.z); v.w = f2tf32(rb1.w);
        *(uint4*)&Bs[0][ldRow + 64][ldCol] = v;
    }
    __syncthreads();

    int cur = 0;
    for (int k0 = 0; k0 < K; k0 += 16) {
        const bool has_next = (k0 + 16) < K;
        if (has_next) {
            int kn = k0 + 16;
            ra0 = *(const float4*)(Aptr  + kn);
            ra1 = *(const float4*)(Aptr2 + kn);
            rb0 = *(const float4*)(Wptr  + kn);
            rb1 = *(const float4*)(Wptr2 + kn);
        }

        const uint32_t aRow = (uint32_t)(cur * BM + wmBase + lRow) * (LDW * 4);
        const uint32_t bRow = (uint32_t)(cur * BN + wnBase + lRow) * (LDW * 4);
#pragma unroll
        for (int kk = 0; kk < 16; kk += 8) {
            const uint32_t kOff = (uint32_t)(kk + lK) * 4;
            uint32_t af[4][4];
#pragma unroll
            for (int mt = 0; mt < 4; mt++) {
                uint32_t addr = AsBase + aRow + (uint32_t)(mt * 16) * (LDW * 4) + kOff;
                ldsm_x4(af[mt][0], af[mt][1], af[mt][2], af[mt][3], addr);
            }
            uint32_t bf[4][2];
#pragma unroll
            for (int pr = 0; pr < 2; pr++) {
                uint32_t addr = BsBase + bRow + (uint32_t)(pr * 16) * (LDW * 4) + kOff;
                ldsm_x4(bf[2 * pr][0], bf[2 * pr + 1][0], bf[2 * pr][1], bf[2 * pr + 1][1], addr);
            }
#pragma unroll
            for (int mt = 0; mt < 4; mt++)
#pragma unroll
                for (int nt = 0; nt < 4; nt++)
                    mma_tf32(acc[mt][nt], af[mt], bf[nt]);
        }

        if (has_next) {
            int nxt = cur ^ 1;
            uint4 v;
            v.x = f2tf32(ra0.x); v.y = f2tf32(ra0.y); v.z = f2tf32(ra0.z); v.w = f2tf32(ra0.w);
            *(uint4*)&As[nxt][ldRow][ldCol] = v;
            v.x = f2tf32(ra1.x); v.y = f2tf32(ra1.y); v.z = f2tf32(ra1.z); v.w = f2tf32(ra1.w);
            *(uint4*)&As[nxt][ldRow + 64][ldCol] = v;
            v.x = f2tf32(rb0.x); v.y = f2tf32(rb0.y); v.z = f2tf32(rb0.z); v.w = f2tf32(rb0.w);
            *(uint4*)&Bs[nxt][ldRow][ldCol] = v;
            v.x = f2tf32(rb1.x); v.y = f2tf32(rb1.y); v.z = f2tf32(rb1.z); v.w = f2tf32(rb1.w);
            *(uint4*)&Bs[nxt][ldRow + 64][ldCol] = v;
        }
        __syncthreads();
        cur ^= 1;
    }

#pragma unroll
    for (int mt = 0; mt < 4; mt++) {
#pragma unroll
        for (int nt = 0; nt < 4; nt++) {
#pragma unroll
            for (int half = 0; half < 2; half++) {
                int row = m0 + wmBase + mt * 16 + grp + half * 8;
                int col = n0 + wnBase + nt * 8 + 2 * tig;
                float v0 = acc[mt][nt][half * 2 + 0];
                float v1 = acc[mt][nt][half * 2 + 1];
                float y0, y1;
                if (mode == 0) {
                    y0 = v0 + bias[col]; y1 = v1 + bias[col + 1];
                } else {
                    float s0 = v0 / (1.0f + __expf(-v0));
                    float s1 = v1 / (1.0f + __expf(-v1));
                    const float2 cc = *(const float2*)(comp + (size_t)row * N + col);
                    y0 = cc.x * s0; y1 = cc.y * s1;
                }
                float2 o; o.x = y0; o.y = y1;
                *(float2*)(C + (size_t)row * N + col) = o;
            }
        }
    }
}

// ---------------- bf16 GEMM (R12-proven): fused alpha+delta ----------------
#define BKB 32

__global__ void __launch_bounds__(256, 2)
gemm_bf16_kernel(const __nv_bfloat16* __restrict__ Xb,
                 const __nv_bfloat16* __restrict__ Wa, const __nv_bfloat16* __restrict__ Wd,
                 const float* __restrict__ ba, const float* __restrict__ bd,
                 float* __restrict__ Ca, float* __restrict__ Cd)
{
    __shared__ uint32_t As[2][BM][LDW];
    __shared__ uint32_t Bs[2][BN][LDW];

    const int K = DIM, N = DIM;

    const int wsel = blockIdx.x >> 3;
    const int ntile = blockIdx.x & 7;
    const __nv_bfloat16* W = wsel ? Wd : Wa;
    const float* bias = wsel ? bd : ba;
    float* C = wsel ? Cd : Ca;

    const int tid  = threadIdx.x;
    const int lane = tid & 31;
    const int warp = tid >> 5;
    const int warpM = warp >> 2;
    const int warpN = warp & 3;
    const int wmBase = warpM * 64;
    const int wnBase = warpN * 32;

    const int m0 = blockIdx.y * BM;
    const int n0 = ntile * BN;

    const int ldRow = tid >> 2;
    const int ldCh  = (tid & 3);
    const __nv_bfloat16* Aptr  = Xb + (size_t)(m0 + ldRow) * K + ldCh * 8;
    const __nv_bfloat16* Aptr2 = Aptr + (size_t)64 * K;
    const __nv_bfloat16* Wptr  = W + (size_t)(n0 + ldRow) * K + ldCh * 8;
    const __nv_bfloat16* Wptr2 = Wptr + (size_t)64 * K;

    const uint32_t AsBase = smem_u32(&As[0][0][0]);
    const uint32_t BsBase = smem_u32(&Bs[0][0][0]);

    const int lRow = (lane & 7) + ((lane >> 3) & 1) * 8;
    const int lKA  = (lane >> 4) * 16;
    const int bRowL = (lane & 7) + ((lane >> 4) << 3);
    const int lKB   = ((lane >> 3) & 1) * 16;

    float acc[4][4][4];
#pragma unroll
    for (int i = 0; i < 4; i++)
#pragma unroll
        for (int j = 0; j < 4; j++)
#pragma unroll
            for (int r = 0; r < 4; r++) acc[i][j][r] = 0.f;

    const int grp = lane >> 2;
    const int tig = lane & 3;

    uint4 qa0 = *(const uint4*)(Aptr);
    uint4 qa1 = *(const uint4*)(Aptr2);
    uint4 qb0 = *(const uint4*)(Wptr);
    uint4 qb1 = *(const uint4*)(Wptr2);
    {
        *(uint4*)&As[0][ldRow][ldCh * 4]      = qa0;
        *(uint4*)&As[0][ldRow + 64][ldCh * 4] = qa1;
        *(uint4*)&Bs[0][ldRow][ldCh * 4]      = qb0;
        *(uint4*)&Bs[0][ldRow + 64][ldCh * 4] = qb1;
    }
    __syncthreads();

    int cur = 0;
    for (int k0 = 0; k0 < K; k0 += BKB) {
        const bool has_next = (k0 + BKB) < K;
        if (has_next) {
            int kn = k0 + BKB;
            qa0 = *(const uint4*)(Aptr  + kn);
            qa1 = *(const uint4*)(Aptr2 + kn);
            qb0 = *(const uint4*)(Wptr  + kn);
            qb1 = *(const uint4*)(Wptr2 + kn);
        }

        const uint32_t aRow = (uint32_t)(cur * BM + wmBase + lRow) * (LDW * 4);
        const uint32_t bRow = (uint32_t)(cur * BN + wnBase + bRowL) * (LDW * 4);
#pragma unroll
        for (int kk = 0; kk < 2; kk++) {
            const uint32_t kByte = (uint32_t)kk * 32;
            uint32_t af[4][4];
#pragma unroll
            for (int mt = 0; mt < 4; mt++) {
                uint32_t addr = AsBase + aRow + (uint32_t)(mt * 16) * (LDW * 4) + kByte + lKA;
                ldsm_x4(af[mt][0], af[mt][1], af[mt][2], af[mt][3], addr);
            }
            uint32_t bf[4][2];
#pragma unroll
            for (int pr = 0; pr < 2; pr++) {
                uint32_t addr = BsBase + bRow + (uint32_t)(pr * 16) * (LDW * 4) + kByte + lKB;
                ldsm_x4(bf[2 * pr][0], bf[2 * pr][1], bf[2 * pr + 1][0], bf[2 * pr + 1][1], addr);
            }
#pragma unroll
            for (int mt = 0; mt < 4; mt++)
#pragma unroll
                for (int nt = 0; nt < 4; nt++)
                    mma_bf16(acc[mt][nt], af[mt], bf[nt]);
        }

        if (has_next) {
            int nxt = cur ^ 1;
            *(uint4*)&As[nxt][ldRow][ldCh * 4]      = qa0;
            *(uint4*)&As[nxt][ldRow + 64][ldCh * 4] = qa1;
            *(uint4*)&Bs[nxt][ldRow][ldCh * 4]      = qb0;
            *(uint4*)&Bs[nxt][ldRow + 64][ldCh * 4] = qb1;
        }
        __syncthreads();
        cur ^= 1;
    }

#pragma unroll
    for (int mt = 0; mt < 4; mt++) {
#pragma unroll
        for (int nt = 0; nt < 4; nt++) {
#pragma unroll
            for (int half = 0; half < 2; half++) {
                int row = m0 + wmBase + mt * 16 + grp + half * 8;
                int col = n0 + wnBase + nt * 8 + 2 * tig;
                float x0 = acc[mt][nt][half * 2 + 0] + bias[col];
                float x1 = acc[mt][nt][half * 2 + 1] + bias[col + 1];
                float y0, y1;
                if (wsel == 0) {
                    y0 = 1.0f + ((x0 > 20.f) ? x0 : log1pf(__expf(x0)));
                    y1 = 1.0f + ((x1 > 20.f) ? x1 : log1pf(__expf(x1)));
                } else {
                    y0 = 1.0f / (1.0f + __expf(-x0));
                    y1 = 1.0f / (1.0f + __expf(-x1));
                }
                float2 o; o.x = y0; o.y = y1;
                *(float2*)(C + (size_t)row * N + col) = o;
            }
        }
    }
}

// ---------------- S1: per-chunk (A,B) accumulation (fast path only) ----------------
// grid (128, NCH) x 128 thr. h_end_chunk = A*h_start + B with a=1-delta, b=delta*cand.
__global__ void __launch_bounds__(128)
scan_chunk_kernel(const float* __restrict__ vx, const float* __restrict__ alpha,
                  const float* __restrict__ delta, const int* __restrict__ rhflag,
                  float* __restrict__ chA, float* __restrict__ chB)
{
    if (*rhflag != 0) return;
    int lane = blockIdx.x * 128 + threadIdx.x;   // 0..16383
    int chunk = blockIdx.y;
    size_t base = (size_t)lane;
    const int tS = chunk * CHL;

    float A = 1.f, B = 0.f;
    float cv[16], ca[16], cd[16], nv[16], na[16], nd[16];
#pragma unroll
    for (int i = 0; i < 16; i++) {
        size_t o = (size_t)(tS + i) * BD + base;
        cv[i] = __ldcs(vx + o); ca[i] = __ldcs(alpha + o); cd[i] = __ldcs(delta + o);
    }

    for (int t0 = 0; t0 < CHL; t0 += 16) {
        const bool more = (t0 + 16) < CHL;
        if (more) {
#pragma unroll
            for (int i = 0; i < 16; i++) {
                size_t o = (size_t)(tS + t0 + 16 + i) * BD + base;
                nv[i] = __ldcs(vx + o); na[i] = __ldcs(alpha + o); nd[i] = __ldcs(delta + o);
            }
        }
        float cb[16];
#pragma unroll
        for (int i = 0; i < 16; i++) cb[i] = cand_fn(cv[i], ca[i]);
#pragma unroll
        for (int i = 0; i < 16; i++) {
            float a = 1.0f - cd[i];
            float b = cd[i] * cb[i];
            A = a * A;
            B = a * B + b;
        }
        if (more) {
#pragma unroll
            for (int i = 0; i < 16; i++) { cv[i] = nv[i]; ca[i] = na[i]; cd[i] = nd[i]; }
        }
    }
    chA[(size_t)chunk * BD + base] = A;
    chB[(size_t)chunk * BD + base] = B;
}

// ---------------- S2: combine chunk (A,B) -> chunk start states ----------------
__global__ void __launch_bounds__(128)
scan_combine_kernel(const float* __restrict__ h0, const float* __restrict__ chA,
                    const float* __restrict__ chB, const int* __restrict__ rhflag,
                    float* __restrict__ hstart, float* __restrict__ out_h)
{
    if (*rhflag != 0) return;
    int lane = blockIdx.x * 128 + threadIdx.x;   // 0..16383
    float h = h0[lane];
    out_h[lane] = h;                             // h[0]
#pragma unroll
    for (int c = 0; c < NCH; c++) {
        hstart[(size_t)c * BD + lane] = h;
        h = chA[(size_t)c * BD + lane] * h + chB[(size_t)c * BD + lane];
    }
}

// ---------------- S3: per-chunk replay + h store + fused compete softmax ----------
__global__ void __launch_bounds__(128)
scan_apply_kernel(const float* __restrict__ vx, const float* __restrict__ alpha,
                  const float* __restrict__ delta, const float* __restrict__ hstart,
                  const int* __restrict__ rhflag,
                  float* __restrict__ out_h, float* __restrict__ cp)
{
    if (*rhflag != 0) return;
    int lane = blockIdx.x * 128 + threadIdx.x;   // 0..16383
    int chunk = blockIdx.y;
    size_t base = (size_t)lane;
    const int tS = chunk * CHL;

    float h = hstart[(size_t)chunk * BD + base];

    float cv[16], ca[16], cd[16], nv[16], na[16], nd[16];
#pragma unroll
    for (int i = 0; i < 16; i++) {
        size_t o = (size_t)(tS + i) * BD + base;
        cv[i] = __ldcs(vx + o); ca[i] = __ldcs(alpha + o); cd[i] = __ldcs(delta + o);
    }

    for (int t0 = 0; t0 < CHL; t0 += 16) {
        const bool more = (t0 + 16) < CHL;
        if (more) {
#pragma unroll
            for (int i = 0; i < 16; i++) {
                size_t o = (size_t)(tS + t0 + 16 + i) * BD + base;
                nv[i] = __ldcs(vx + o); na[i] = __ldcs(alpha + o); nd[i] = __ldcs(delta + o);
            }
        }
        float cb[16];
#pragma unroll
        for (int i = 0; i < 16; i++) cb[i] = cand_fn(cv[i], ca[i]);

        float hr[16];
#pragma unroll
        for (int i = 0; i < 16; i++) {
            h = h + cd[i] * (cb[i] - h);
            hr[i] = h;
        }

#pragma unroll
        for (int i = 0; i < 16; i++) {
            size_t o = (size_t)(tS + t0 + i) * BD + base;
            __stcs(out_h + o + BD, hr[i]);
            float m = hr[i];
#pragma unroll
            for (int of = 16; of > 0; of >>= 1) m = fmaxf(m, __shfl_xor_sync(0xffffffffu, m, of));
            float e = __expf(hr[i] - m);
            float s = e;
#pragma unroll
            for (int of = 16; of > 0; of >>= 1) s += __shfl_xor_sync(0xffffffffu, s, of);
            __stcs(cp + o, e / s);
        }

        if (more) {
#pragma unroll
            for (int i = 0; i < 16; i++) { cv[i] = nv[i]; ca[i] = na[i]; cd[i] = nd[i]; }
        }
    }
}

// ---------------- fallback: general sequential scan (r_h != 0 only) ----------------
__global__ void __launch_bounds__(64)
scan_seq_kernel(const float* __restrict__ vx, const float* __restrict__ alpha,
                const float* __restrict__ delta, const float* __restrict__ h0,
                const float* __restrict__ r_h, float* __restrict__ out_h,
                float* __restrict__ cp, const int* __restrict__ rhflag)
{
    if (*rhflag == 0) return;
    int gtid = blockIdx.x * 64 + threadIdx.x;
    int d = gtid & 1023;
    size_t base = (size_t)gtid;

    float rh = r_h[d];
    float h = h0[base];
    out_h[base] = h;

    float cv[16], ca[16], cd[16], nv[16], na[16], nd[16];
#pragma unroll
    for (int i = 0; i < 16; i++) {
        size_t o = (size_t)i * BD + base;
        cv[i] = __ldcs(vx + o); ca[i] = __ldcs(alpha + o); cd[i] = __ldcs(delta + o);
    }

    for (int t0 = 0; t0 < TT; t0 += 16) {
        const bool more = (t0 + 16) < TT;
        if (more) {
#pragma unroll
            for (int i = 0; i < 16; i++) {
                size_t o = (size_t)(t0 + 16 + i) * BD + base;
                nv[i] = __ldcs(vx + o); na[i] = __ldcs(alpha + o); nd[i] = __ldcs(delta + o);
            }
        }
        float hr[16];
#pragma unroll
        for (int i = 0; i < 16; i++) {
            float v = cv[i] + rh * h;
            float c = cand_fn(v, ca[i]);
            h = h + cd[i] * (c - h);
            hr[i] = h;
        }
#pragma unroll
        for (int i = 0; i < 16; i++) {
            size_t o = (size_t)(t0 + i) * BD + base;
            __stcs(out_h + o + BD, hr[i]);
            float m = hr[i];
#pragma unroll
            for (int of = 16; of > 0; of >>= 1) m = fmaxf(m, __shfl_xor_sync(0xffffffffu, m, of));
            float e = __expf(hr[i] - m);
            float s = e;
#pragma unroll
            for (int of = 16; of > 0; of >>= 1) s += __shfl_xor_sync(0xffffffffu, s, of);
            __stcs(cp + o, e / s);
        }
        if (more) {
#pragma unroll
            for (int i = 0; i < 16; i++) { cv[i] = nv[i]; ca[i] = na[i]; cd[i] = nd[i]; }
        }
    }
}

// ---------------- launch ----------------
extern "C" void kernel_launch(void* const* d_in, const int* in_sizes, int n_in,
                              void* d_out, int out_size)
{
    const float* x       = (const float*)d_in[0];   // [T,B,D]
    const float* h0      = (const float*)d_in[1];   // [B,D]
    const float* W_x     = (const float*)d_in[2];   // [D,D]
    const float* r_h     = (const float*)d_in[3];   // [D]
    const float* b       = (const float*)d_in[4];   // [D]
    const float* W_alpha = (const float*)d_in[5];
    const float* b_alpha = (const float*)d_in[6];
    const float* W_delta = (const float*)d_in[7];
    const float* b_delta = (const float*)d_in[8];
    const float* W_out   = (const float*)d_in[9];

    float* out = (float*)d_out;
    float* out_h = out;                                  // [T+1,B,D]
    float* out_y = out + (size_t)(TT + 1) * BD;          // [T,B,D]

    float *vx, *al, *dl, *cpt, *chA, *chB, *hst;
    __nv_bfloat16 *xb, *wab, *wdb;
    int* rhf;
    cudaGetSymbolAddress((void**)&vx, g_vx);
    cudaGetSymbolAddress((void**)&al, g_alpha);
    cudaGetSymbolAddress((void**)&dl, g_delta);
    cudaGetSymbolAddress((void**)&cpt, g_compete);
    cudaGetSymbolAddress((void**)&xb, g_xb);
    cudaGetSymbolAddress((void**)&wab, g_wab);
    cudaGetSymbolAddress((void**)&wdb, g_wdb);
    cudaGetSymbolAddress((void**)&rhf, g_rhflag);
    cudaGetSymbolAddress((void**)&chA, g_chA);
    cudaGetSymbolAddress((void**)&chB, g_chB);
    cudaGetSymbolAddress((void**)&hst, g_hstart);

    // 0) r_h flag + bf16 converts
    rh_flag_kernel<<<1, 256>>>(r_h, rhf);
    const int XN8 = MROWS * DIM / 8;
    const int WN8 = DIM * DIM / 8;
    bf16_convert_kernel<<<(XN8 + 255) / 256, 256>>>(x, xb, XN8);
    bf16_convert_kernel<<<(WN8 + 255) / 256, 256>>>(W_alpha, wab, WN8);
    bf16_convert_kernel<<<(WN8 + 255) / 256, 256>>>(W_delta, wdb, WN8);

    // 1) vx projection (tf32)
    dim3 vgrid(DIM / BN, MROWS / BM);          // (8, 128)
    gemm_tf32_kernel<<<vgrid, 256>>>(x, W_x, b, nullptr, vx, 0);

    // 2) alpha + delta projections (bf16)
    dim3 agrid(2 * (DIM / BN), MROWS / BM);    // (16, 128)
    gemm_bf16_kernel<<<agrid, 256>>>(xb, wab, wdb, b_alpha, b_delta, al, dl);

    // 3) scan: fast path = parallel chunked linear scan (8x T-parallelism);
    //    fallback sequential kernel handles r_h != 0 (no-op otherwise)
    dim3 cgrid(BD / 128, NCH);                 // (128, 8)
    scan_chunk_kernel<<<cgrid, 128>>>(vx, al, dl, rhf, chA, chB);
    scan_combine_kernel<<<BD / 128, 128>>>(h0, chA, chB, rhf, hst, out_h);
    scan_apply_kernel<<<cgrid, 128>>>(vx, al, dl, hst, rhf, out_h, cpt);
    scan_seq_kernel<<<256, 64>>>(vx, al, dl, h0, r_h, out_h, cpt, rhf);

    // 4) output GEMM with compete*silu epilogue (tf32)
    gemm_tf32_kernel<<<vgrid, 256>>>(out_h + BD, W_out, nullptr, cpt, out_y, 3);
}